// round 1
// baseline (speedup 1.0000x reference)
#include <cuda_runtime.h>
#include <math.h>

// Problem constants
#define Bv   2
#define Sv   2048
#define Dv   4096
#define Hv   32
#define KVHv 8
#define HDv  128
#define Mv   (Bv * Sv)       // 4096 rows (b,s)
#define NQ   (Hv * HDv)      // 4096
#define NKV  (KVHv * HDv)    // 1024

// Scratch (static __device__ arrays; allocation APIs are forbidden)
__device__ float g_q[(size_t)Mv * NQ];     // 64 MB
__device__ float g_k[(size_t)Mv * NKV];    // 16 MB
__device__ float g_v[(size_t)Mv * NKV];    // 16 MB
__device__ float g_att[(size_t)Mv * NQ];   // 64 MB

// ---------------------------------------------------------------------------
// SGEMM: C[M,N] = A[M,K] @ W[N,K]^T   (both row-major, "NT" gemm)
// 128x128 block tile, K-tile 8, 256 threads, 8x8 per-thread microtile.
// M,N multiples of 128; K multiple of 8 (all true here).
// ---------------------------------------------------------------------------
__global__ __launch_bounds__(256) void sgemm_nt(
    const float* __restrict__ A, const float* __restrict__ W,
    float* __restrict__ C, int M, int N, int K)
{
    __shared__ float As[8][128];
    __shared__ float Bs[8][128];

    const int tid = threadIdx.x;
    const int tx = tid & 15;
    const int ty = tid >> 4;
    const int m0 = blockIdx.y * 128;
    const int n0 = blockIdx.x * 128;

    const int lr = tid >> 1;          // 0..127 (row within tile)
    const int lc = (tid & 1) * 4;     // 0 or 4 (col4 within k-tile)

    const float* Ag = A + (size_t)(m0 + lr) * K + lc;
    const float* Bg = W + (size_t)(n0 + lr) * K + lc;

    float acc[8][8];
#pragma unroll
    for (int i = 0; i < 8; i++)
#pragma unroll
        for (int j = 0; j < 8; j++) acc[i][j] = 0.f;

    for (int k0 = 0; k0 < K; k0 += 8) {
        float4 av = *(const float4*)(Ag + k0);
        float4 bv = *(const float4*)(Bg + k0);
        __syncthreads();   // previous tile's reads complete before overwrite
        As[lc + 0][lr] = av.x; As[lc + 1][lr] = av.y;
        As[lc + 2][lr] = av.z; As[lc + 3][lr] = av.w;
        Bs[lc + 0][lr] = bv.x; Bs[lc + 1][lr] = bv.y;
        Bs[lc + 2][lr] = bv.z; Bs[lc + 3][lr] = bv.w;
        __syncthreads();
#pragma unroll
        for (int kk = 0; kk < 8; kk++) {
            float a[8], b[8];
            *(float4*)(a)     = *(const float4*)&As[kk][ty * 8];
            *(float4*)(a + 4) = *(const float4*)&As[kk][ty * 8 + 4];
            *(float4*)(b)     = *(const float4*)&Bs[kk][tx * 8];
            *(float4*)(b + 4) = *(const float4*)&Bs[kk][tx * 8 + 4];
#pragma unroll
            for (int i = 0; i < 8; i++)
#pragma unroll
                for (int j = 0; j < 8; j++) acc[i][j] += a[i] * b[j];
        }
    }

#pragma unroll
    for (int i = 0; i < 8; i++) {
        float* Cp = C + (size_t)(m0 + ty * 8 + i) * N + n0 + tx * 8;
        *(float4*)(Cp)     = make_float4(acc[i][0], acc[i][1], acc[i][2], acc[i][3]);
        *(float4*)(Cp + 4) = make_float4(acc[i][4], acc[i][5], acc[i][6], acc[i][7]);
    }
}

// ---------------------------------------------------------------------------
// RoPE applied in-place. Layout: t[m][h*128 + 2i], t[m][h*128 + 2i+1] pairs,
// cos/sin indexed [s][i] with s = m % S.
// ---------------------------------------------------------------------------
__global__ void rope_kernel(float* __restrict__ t,
                            const float* __restrict__ cs,
                            const float* __restrict__ sn,
                            int nheads)
{
    long idx = (long)blockIdx.x * blockDim.x + threadIdx.x;
    long total = (long)Mv * nheads * (HDv / 2);
    if (idx >= total) return;
    int i = (int)(idx & 63);
    long t2 = idx >> 6;
    int h = (int)(t2 % nheads);
    int m = (int)(t2 / nheads);
    int s = m % Sv;
    float c = cs[s * 64 + i];
    float si = sn[s * 64 + i];
    float* p = t + (size_t)m * (nheads * HDv) + h * HDv + 2 * i;
    float re = p[0], im = p[1];
    p[0] = re * c - im * si;
    p[1] = re * si + im * c;
}

// ---------------------------------------------------------------------------
// Fused causal flash attention, fp32.
// Block = (q-tile of 64 rows) x (head) x (batch). 256 threads.
// Q,K stored transposed in smem ([128][64]) for float4 fragment loads.
// ---------------------------------------------------------------------------
__global__ __launch_bounds__(256) void flash_kernel(
    const float* __restrict__ Q, const float* __restrict__ Kg,
    const float* __restrict__ Vg, float* __restrict__ O)
{
    extern __shared__ float sm[];
    float* Qt   = sm;                 // [128][64]  (transposed)
    float* Kt   = Qt + 128 * 64;      // [128][64]  (transposed)
    float* Vs   = Kt + 128 * 64;      // [64][128]
    float* Ss   = Vs + 64 * 128;      // [64][64]
    float* m_s  = Ss + 64 * 64;       // [64]
    float* l_s  = m_s + 64;           // [64]
    float* al_s = l_s + 64;           // [64]

    const int q0 = blockIdx.x * 64;
    const int h  = blockIdx.y;
    const int b  = blockIdx.z;
    const int kvh = h / (Hv / KVHv);
    const int tid = threadIdx.x;
    const int tx = tid & 15;
    const int ty = tid >> 4;
    const float scale = 0.08838834764831845f;  // 1/sqrt(128)

    // Load Q tile transposed: Qt[d][r] = Q[q0+r][h*128+d]
    const float* Qb = Q + (size_t)(b * Sv + q0) * NQ + h * HDv;
    for (int idx = tid; idx < 64 * 32; idx += 256) {
        int r = idx >> 5, c4 = (idx & 31) * 4;
        float4 qv = *(const float4*)(Qb + (size_t)r * NQ + c4);
        Qt[(c4 + 0) * 64 + r] = qv.x;
        Qt[(c4 + 1) * 64 + r] = qv.y;
        Qt[(c4 + 2) * 64 + r] = qv.z;
        Qt[(c4 + 3) * 64 + r] = qv.w;
    }
    if (tid < 64) { m_s[tid] = -1e30f; l_s[tid] = 0.f; }

    float acc[4][8];
#pragma unroll
    for (int i = 0; i < 4; i++)
#pragma unroll
        for (int j = 0; j < 8; j++) acc[i][j] = 0.f;

    const int r4 = tid >> 2;   // softmax row (0..63)
    const int q4 = tid & 3;    // quad lane

    const int ktiles = q0 / 64 + 1;
    for (int kt = 0; kt < ktiles; kt++) {
        const int k0 = kt * 64;
        __syncthreads();   // previous tile's Ss/Vs reads done

        const float* Kb = Kg + (size_t)(b * Sv + k0) * NKV + kvh * HDv;
        const float* Vb = Vg + (size_t)(b * Sv + k0) * NKV + kvh * HDv;
        for (int idx = tid; idx < 64 * 32; idx += 256) {
            int r = idx >> 5, c4 = (idx & 31) * 4;
            float4 kv = *(const float4*)(Kb + (size_t)r * NKV + c4);
            Kt[(c4 + 0) * 64 + r] = kv.x;
            Kt[(c4 + 1) * 64 + r] = kv.y;
            Kt[(c4 + 2) * 64 + r] = kv.z;
            Kt[(c4 + 3) * 64 + r] = kv.w;
            *(float4*)&Vs[r * 128 + c4] = *(const float4*)(Vb + (size_t)r * NKV + c4);
        }
        __syncthreads();

        // Scores: this thread computes rows ty*4+i, cols tx*4+j of 64x64 tile
        float sc[4][4];
#pragma unroll
        for (int i = 0; i < 4; i++)
#pragma unroll
            for (int j = 0; j < 4; j++) sc[i][j] = 0.f;
#pragma unroll 4
        for (int k = 0; k < 128; k++) {
            float a[4], bb[4];
            *(float4*)a  = *(const float4*)&Qt[k * 64 + ty * 4];
            *(float4*)bb = *(const float4*)&Kt[k * 64 + tx * 4];
#pragma unroll
            for (int i = 0; i < 4; i++)
#pragma unroll
                for (int j = 0; j < 4; j++) sc[i][j] += a[i] * bb[j];
        }
#pragma unroll
        for (int i = 0; i < 4; i++) {
            int qi = q0 + ty * 4 + i;
#pragma unroll
            for (int j = 0; j < 4; j++) {
                int kj = k0 + tx * 4 + j;
                float v = sc[i][j] * scale;
                if (kj > qi) v = -1e30f;     // causal mask (== ref's -1e9 after softmax)
                Ss[(ty * 4 + i) * 64 + tx * 4 + j] = v;
            }
        }
        __syncthreads();

        // Online softmax: quad of 4 threads per row, 16 cols each
        {
            float* row = Ss + r4 * 64 + q4 * 16;
            float mx = -1e30f;
#pragma unroll
            for (int c = 0; c < 16; c++) mx = fmaxf(mx, row[c]);
            mx = fmaxf(mx, __shfl_xor_sync(0xffffffffu, mx, 1));
            mx = fmaxf(mx, __shfl_xor_sync(0xffffffffu, mx, 2));
            float m_old = m_s[r4];
            float m_new = fmaxf(m_old, mx);
            float sum = 0.f;
#pragma unroll
            for (int c = 0; c < 16; c++) {
                float p = __expf(row[c] - m_new);
                row[c] = p;
                sum += p;
            }
            sum += __shfl_xor_sync(0xffffffffu, sum, 1);
            sum += __shfl_xor_sync(0xffffffffu, sum, 2);
            if (q4 == 0) {
                float alpha = __expf(m_old - m_new);   // 0 on first tile
                m_s[r4] = m_new;
                l_s[r4] = l_s[r4] * alpha + sum;
                al_s[r4] = alpha;
            }
        }
        __syncthreads();

        // Rescale + PV: rows ty*4+i, cols tx*8+j
        float alw[4];
#pragma unroll
        for (int i = 0; i < 4; i++) alw[i] = al_s[ty * 4 + i];
#pragma unroll
        for (int i = 0; i < 4; i++)
#pragma unroll
            for (int j = 0; j < 8; j++) acc[i][j] *= alw[i];
#pragma unroll 4
        for (int kk = 0; kk < 64; kk++) {
            float p[4], vv[8];
#pragma unroll
            for (int i = 0; i < 4; i++) p[i] = Ss[(ty * 4 + i) * 64 + kk];
            *(float4*)(vv)     = *(const float4*)&Vs[kk * 128 + tx * 8];
            *(float4*)(vv + 4) = *(const float4*)&Vs[kk * 128 + tx * 8 + 4];
#pragma unroll
            for (int i = 0; i < 4; i++)
#pragma unroll
                for (int j = 0; j < 8; j++) acc[i][j] += p[i] * vv[j];
        }
    }

    // Output: divide by l, write attn_out
    float* Ob = O + (size_t)(b * Sv + q0) * NQ + h * HDv;
#pragma unroll
    for (int i = 0; i < 4; i++) {
        float inv = 1.f / l_s[ty * 4 + i];
        float* op = Ob + (size_t)(ty * 4 + i) * NQ + tx * 8;
        *(float4*)(op)     = make_float4(acc[i][0] * inv, acc[i][1] * inv,
                                         acc[i][2] * inv, acc[i][3] * inv);
        *(float4*)(op + 4) = make_float4(acc[i][4] * inv, acc[i][5] * inv,
                                         acc[i][6] * inv, acc[i][7] * inv);
    }
}

// ---------------------------------------------------------------------------
// Launch
// Inputs: 0=x, 1=freqs_cos, 2=freqs_sin, 3=positions(unused: arange),
//         4=mask(unused: causal), 5=wq, 6=wk, 7=wv, 8=wo
// ---------------------------------------------------------------------------
extern "C" void kernel_launch(void* const* d_in, const int* in_sizes, int n_in,
                              void* d_out, int out_size)
{
    const float* x  = (const float*)d_in[0];
    const float* fc = (const float*)d_in[1];
    const float* fs = (const float*)d_in[2];
    const float* wq = (const float*)d_in[5];
    const float* wk = (const float*)d_in[6];
    const float* wv = (const float*)d_in[7];
    const float* wo = (const float*)d_in[8];
    float* out = (float*)d_out;

    float *q, *k, *v, *att;
    cudaGetSymbolAddress((void**)&q,   g_q);
    cudaGetSymbolAddress((void**)&k,   g_k);
    cudaGetSymbolAddress((void**)&v,   g_v);
    cudaGetSymbolAddress((void**)&att, g_att);

    dim3 blk(256);

    // QKV projections
    sgemm_nt<<<dim3(NQ / 128,  Mv / 128), blk>>>(x, wq, q, Mv, NQ,  Dv);
    sgemm_nt<<<dim3(NKV / 128, Mv / 128), blk>>>(x, wk, k, Mv, NKV, Dv);
    sgemm_nt<<<dim3(NKV / 128, Mv / 128), blk>>>(x, wv, v, Mv, NKV, Dv);

    // RoPE on Q and K
    {
        long nq_pairs = (long)Mv * Hv * (HDv / 2);
        long nk_pairs = (long)Mv * KVHv * (HDv / 2);
        rope_kernel<<<(unsigned)((nq_pairs + 255) / 256), 256>>>(q, fc, fs, Hv);
        rope_kernel<<<(unsigned)((nk_pairs + 255) / 256), 256>>>(k, fc, fs, KVHv);
    }

    // Fused causal flash attention
    {
        const int smem_bytes = (128 * 64 + 128 * 64 + 64 * 128 + 64 * 64 + 3 * 64) * 4;
        cudaFuncSetAttribute(flash_kernel,
                             cudaFuncAttributeMaxDynamicSharedMemorySize, smem_bytes);
        flash_kernel<<<dim3(Sv / 64, Hv, Bv), blk, smem_bytes>>>(q, k, v, att);
    }

    // Output projection
    sgemm_nt<<<dim3(NQ / 128, Mv / 128), blk>>>(att, wo, out, Mv, NQ, Dv);
}

// round 3
// speedup vs baseline: 1.8108x; 1.8108x over previous
#include <cuda_runtime.h>
#include <cuda_bf16.h>
#include <cstdint>
#include <math.h>

// Problem constants
#define Bv   2
#define Sv   2048
#define Dv   4096
#define Hv   32
#define KVHv 8
#define HDv  128
#define Mv   (Bv * Sv)       // 4096
#define NQ   (Hv * HDv)      // 4096
#define NKV  (KVHv * HDv)    // 1024

// fp32 scratch
__device__ float g_q[(size_t)Mv * NQ];
__device__ float g_k[(size_t)Mv * NKV];
__device__ float g_v[(size_t)Mv * NKV];
__device__ float g_att[(size_t)Mv * NQ];
// bf16 split-precision scratch (hi + lo)
__device__ __nv_bfloat16 g_x_hi[(size_t)Mv * Dv],  g_x_lo[(size_t)Mv * Dv];
__device__ __nv_bfloat16 g_wq_hi[(size_t)NQ * Dv], g_wq_lo[(size_t)NQ * Dv];
__device__ __nv_bfloat16 g_wk_hi[(size_t)NKV * Dv], g_wk_lo[(size_t)NKV * Dv];
__device__ __nv_bfloat16 g_wv_hi[(size_t)NKV * Dv], g_wv_lo[(size_t)NKV * Dv];
__device__ __nv_bfloat16 g_wo_hi[(size_t)Dv * NQ], g_wo_lo[(size_t)Dv * NQ];
__device__ __nv_bfloat16 g_at_hi[(size_t)Mv * NQ], g_at_lo[(size_t)Mv * NQ];

// ---------------------------------------------------------------------------
// Helpers (compute_103-safe: cp.async + mma.sync only, NO tcgen05)
// ---------------------------------------------------------------------------
__device__ __forceinline__ uint32_t smem_u32(const void* p) {
    uint32_t a;
    asm("{ .reg .u64 t; cvta.to.shared.u64 t, %1; cvt.u32.u64 %0, t; }" : "=r"(a) : "l"(p));
    return a;
}
__device__ __forceinline__ void cp16(uint32_t dst, const void* src) {
    asm volatile("cp.async.cg.shared.global [%0], [%1], 16;" :: "r"(dst), "l"(src));
}
#define CP_COMMIT() asm volatile("cp.async.commit_group;" ::: "memory")
#define CP_WAIT2()  asm volatile("cp.async.wait_group 2;" ::: "memory")

__device__ __forceinline__ uint32_t lds32(uint32_t a) {
    uint32_t v;
    asm volatile("ld.shared.b32 %0, [%1];" : "=r"(v) : "r"(a));
    return v;
}
__device__ __forceinline__ void mma_bf16(float* c, const uint32_t* a, const uint32_t* b) {
    asm volatile("mma.sync.aligned.m16n8k16.row.col.f32.bf16.bf16.f32 "
        "{%0,%1,%2,%3}, {%4,%5,%6,%7}, {%8,%9}, {%0,%1,%2,%3};"
        : "+f"(c[0]), "+f"(c[1]), "+f"(c[2]), "+f"(c[3])
        : "r"(a[0]), "r"(a[1]), "r"(a[2]), "r"(a[3]), "r"(b[0]), "r"(b[1]));
}

// ---------------------------------------------------------------------------
// Split fp32 -> bf16 hi/lo
// ---------------------------------------------------------------------------
__global__ void cvt_split(const float* __restrict__ in,
                          __nv_bfloat16* __restrict__ hi,
                          __nv_bfloat16* __restrict__ lo, long n4) {
    long i = (long)blockIdx.x * blockDim.x + threadIdx.x;
    if (i >= n4) return;
    float4 v = ((const float4*)in)[i];
    __nv_bfloat16 h[4], l[4];
    float vv[4] = {v.x, v.y, v.z, v.w};
#pragma unroll
    for (int j = 0; j < 4; j++) {
        h[j] = __float2bfloat16(vv[j]);
        l[j] = __float2bfloat16(vv[j] - __bfloat162float(h[j]));
    }
    ((__nv_bfloat162*)hi)[i * 2]     = __nv_bfloat162(h[0], h[1]);
    ((__nv_bfloat162*)hi)[i * 2 + 1] = __nv_bfloat162(h[2], h[3]);
    ((__nv_bfloat162*)lo)[i * 2]     = __nv_bfloat162(l[0], l[1]);
    ((__nv_bfloat162*)lo)[i * 2 + 1] = __nv_bfloat162(l[2], l[3]);
}

// ---------------------------------------------------------------------------
// HMMA bf16x3 GEMM: C[M,N] = A[M,K] @ B[N,K]^T with fp32-equivalent accuracy.
// 128x128 CTA tile, BK=32, 4-stage cp.async pipeline, 8 warps (64x32 each).
// smem rows padded to 80B: the m16n8k16 fragment pattern (8 rows x 4 words)
// hits all 32 banks exactly once -> conflict-free without ldmatrix.
// ---------------------------------------------------------------------------
#define BM 128
#define BN 128
#define BK 32
#define STAGES 4
#define ROW_STRIDE 80                  // 64B data + 16B pad
#define TILE_SM   (128 * ROW_STRIDE)   // 10240 B (one 128x32 bf16 tile)
#define STAGE_SM  (4 * TILE_SM)        // Ahi, Alo, Bhi, Blo = 40960 B
#define GEMM_SMEM (STAGES * STAGE_SM)  // 163840 B

__device__ __forceinline__ void load_stage(
    uint32_t sbase,
    const __nv_bfloat16* __restrict__ Ahi, const __nv_bfloat16* __restrict__ Alo,
    const __nv_bfloat16* __restrict__ Bhi, const __nv_bfloat16* __restrict__ Blo,
    int m0, int n0, int k0, int K, int tid)
{
    // 2048 x 16B chunks; tile = j>>1 is compile-time per unrolled j.
#pragma unroll
    for (int j = 0; j < 8; j++) {
        const int tile = j >> 1;                    // 0:Ahi 1:Alo 2:Bhi 3:Blo
        const int cc = tid + (j & 1) * 256;         // 0..511 within tile
        const int row = cc >> 2;
        const int c16 = cc & 3;
        const uint32_t soff = sbase + tile * TILE_SM + row * ROW_STRIDE + c16 * 16;
        const __nv_bfloat16* g =
            (tile == 0) ? Ahi : (tile == 1) ? Alo : (tile == 2) ? Bhi : Blo;
        const int grow = (tile < 2) ? (m0 + row) : (n0 + row);
        cp16(soff, g + (size_t)grow * K + k0 + c16 * 8);
    }
}

__global__ __launch_bounds__(256) void gemm_hmma_x3(
    const __nv_bfloat16* __restrict__ Ahi, const __nv_bfloat16* __restrict__ Alo,
    const __nv_bfloat16* __restrict__ Bhi, const __nv_bfloat16* __restrict__ Blo,
    float* __restrict__ C, int N, int K)
{
    extern __shared__ char smem[];
    const uint32_t sb = smem_u32(smem);
    const int tid = threadIdx.x;
    const int wid = tid >> 5, lane = tid & 31;
    const int wm = wid & 1;        // 2 warps in M
    const int wn = wid >> 1;       // 4 warps in N
    const int lr = lane >> 2;      // 0..7
    const int lc4 = (lane & 3) * 4;
    const int m0 = blockIdx.y * BM, n0 = blockIdx.x * BN;

    float acc[4][4][4];
#pragma unroll
    for (int mt = 0; mt < 4; mt++)
#pragma unroll
        for (int nt = 0; nt < 4; nt++)
#pragma unroll
            for (int r = 0; r < 4; r++) acc[mt][nt][r] = 0.f;

    const int NIT = K / BK;

    // prologue: prefetch 3 stages
#pragma unroll
    for (int p = 0; p < STAGES - 1; p++) {
        load_stage(sb + p * STAGE_SM, Ahi, Alo, Bhi, Blo, m0, n0, p * BK, K, tid);
        CP_COMMIT();
    }

    for (int it = 0; it < NIT; ++it) {
        CP_WAIT2();            // stage `it` resident (uniform group counting)
        __syncthreads();       // also: everyone done reading buf (it+3)%4 at it-1

        const int pre = it + STAGES - 1;
        if (pre < NIT)
            load_stage(sb + (pre % STAGES) * STAGE_SM,
                       Ahi, Alo, Bhi, Blo, m0, n0, pre * BK, K, tid);
        CP_COMMIT();           // always commit to keep counting fixed

        const uint32_t sA = sb + (it % STAGES) * STAGE_SM;
        const uint32_t sB = sA + 2 * TILE_SM;
#pragma unroll
        for (int kk = 0; kk < 2; kk++) {   // two k16 slices in BK=32
            uint32_t ah[4][4], al[4][4], bh[4][2], bl[4][2];
#pragma unroll
            for (int mt = 0; mt < 4; mt++) {
                uint32_t base = sA + (wm * 64 + mt * 16 + lr) * ROW_STRIDE + kk * 32 + lc4;
                ah[mt][0] = lds32(base);
                ah[mt][1] = lds32(base + 8 * ROW_STRIDE);
                ah[mt][2] = lds32(base + 16);
                ah[mt][3] = lds32(base + 8 * ROW_STRIDE + 16);
                base += TILE_SM;
                al[mt][0] = lds32(base);
                al[mt][1] = lds32(base + 8 * ROW_STRIDE);
                al[mt][2] = lds32(base + 16);
                al[mt][3] = lds32(base + 8 * ROW_STRIDE + 16);
            }
#pragma unroll
            for (int nt = 0; nt < 4; nt++) {
                uint32_t base = sB + (wn * 32 + nt * 8 + lr) * ROW_STRIDE + kk * 32 + lc4;
                bh[nt][0] = lds32(base);
                bh[nt][1] = lds32(base + 16);
                base += TILE_SM;
                bl[nt][0] = lds32(base);
                bl[nt][1] = lds32(base + 16);
            }
#pragma unroll
            for (int mt = 0; mt < 4; mt++)
#pragma unroll
                for (int nt = 0; nt < 4; nt++) {
                    mma_bf16(acc[mt][nt], ah[mt], bh[nt]);
                    mma_bf16(acc[mt][nt], ah[mt], bl[nt]);
                    mma_bf16(acc[mt][nt], al[mt], bh[nt]);
                }
        }
    }

    // epilogue
#pragma unroll
    for (int mt = 0; mt < 4; mt++) {
        const int row = m0 + wm * 64 + mt * 16 + lr;
#pragma unroll
        for (int nt = 0; nt < 4; nt++) {
            const int col = n0 + wn * 32 + nt * 8 + (lane & 3) * 2;
            float2* p0 = (float2*)&C[(size_t)row * N + col];
            float2* p1 = (float2*)&C[(size_t)(row + 8) * N + col];
            *p0 = make_float2(acc[mt][nt][0], acc[mt][nt][1]);
            *p1 = make_float2(acc[mt][nt][2], acc[mt][nt][3]);
        }
    }
}

// ---------------------------------------------------------------------------
// RoPE (in-place, fp32)
// ---------------------------------------------------------------------------
__global__ void rope_kernel(float* __restrict__ t,
                            const float* __restrict__ cs,
                            const float* __restrict__ sn, int nheads)
{
    long idx = (long)blockIdx.x * blockDim.x + threadIdx.x;
    long total = (long)Mv * nheads * (HDv / 2);
    if (idx >= total) return;
    int i = (int)(idx & 63);
    long t2 = idx >> 6;
    int h = (int)(t2 % nheads);
    int m = (int)(t2 / nheads);
    int s = m % Sv;
    float c = cs[s * 64 + i];
    float si = sn[s * 64 + i];
    float* p = t + (size_t)m * (nheads * HDv) + h * HDv + 2 * i;
    float re = p[0], im = p[1];
    p[0] = re * c - im * si;
    p[1] = re * si + im * c;
}

// ---------------------------------------------------------------------------
// Fused causal flash attention, fp32 SIMT (unchanged; correct at 2.3e-6)
// ---------------------------------------------------------------------------
__global__ __launch_bounds__(256) void flash_kernel(
    const float* __restrict__ Q, const float* __restrict__ Kg,
    const float* __restrict__ Vg, float* __restrict__ O)
{
    extern __shared__ float sm[];
    float* Qt   = sm;
    float* Kt   = Qt + 128 * 64;
    float* Vs   = Kt + 128 * 64;
    float* Ss   = Vs + 64 * 128;
    float* m_s  = Ss + 64 * 64;
    float* l_s  = m_s + 64;
    float* al_s = l_s + 64;

    const int q0 = blockIdx.x * 64;
    const int h  = blockIdx.y;
    const int b  = blockIdx.z;
    const int kvh = h / (Hv / KVHv);
    const int tid = threadIdx.x;
    const int tx = tid & 15;
    const int ty = tid >> 4;
    const float scale = 0.08838834764831845f;

    const float* Qb = Q + (size_t)(b * Sv + q0) * NQ + h * HDv;
    for (int idx = tid; idx < 64 * 32; idx += 256) {
        int r = idx >> 5, c4 = (idx & 31) * 4;
        float4 qv = *(const float4*)(Qb + (size_t)r * NQ + c4);
        Qt[(c4 + 0) * 64 + r] = qv.x;
        Qt[(c4 + 1) * 64 + r] = qv.y;
        Qt[(c4 + 2) * 64 + r] = qv.z;
        Qt[(c4 + 3) * 64 + r] = qv.w;
    }
    if (tid < 64) { m_s[tid] = -1e30f; l_s[tid] = 0.f; }

    float acc[4][8];
#pragma unroll
    for (int i = 0; i < 4; i++)
#pragma unroll
        for (int j = 0; j < 8; j++) acc[i][j] = 0.f;

    const int r4 = tid >> 2;
    const int q4 = tid & 3;

    const int ktiles = q0 / 64 + 1;
    for (int kt = 0; kt < ktiles; kt++) {
        const int k0 = kt * 64;
        __syncthreads();

        const float* Kb = Kg + (size_t)(b * Sv + k0) * NKV + kvh * HDv;
        const float* Vb = Vg + (size_t)(b * Sv + k0) * NKV + kvh * HDv;
        for (int idx = tid; idx < 64 * 32; idx += 256) {
            int r = idx >> 5, c4 = (idx & 31) * 4;
            float4 kv = *(const float4*)(Kb + (size_t)r * NKV + c4);
            Kt[(c4 + 0) * 64 + r] = kv.x;
            Kt[(c4 + 1) * 64 + r] = kv.y;
            Kt[(c4 + 2) * 64 + r] = kv.z;
            Kt[(c4 + 3) * 64 + r] = kv.w;
            *(float4*)&Vs[r * 128 + c4] = *(const float4*)(Vb + (size_t)r * NKV + c4);
        }
        __syncthreads();

        float sc[4][4];
#pragma unroll
        for (int i = 0; i < 4; i++)
#pragma unroll
            for (int j = 0; j < 4; j++) sc[i][j] = 0.f;
#pragma unroll 4
        for (int k = 0; k < 128; k++) {
            float a[4], bb[4];
            *(float4*)a  = *(const float4*)&Qt[k * 64 + ty * 4];
            *(float4*)bb = *(const float4*)&Kt[k * 64 + tx * 4];
#pragma unroll
            for (int i = 0; i < 4; i++)
#pragma unroll
                for (int j = 0; j < 4; j++) sc[i][j] += a[i] * bb[j];
        }
#pragma unroll
        for (int i = 0; i < 4; i++) {
            int qi = q0 + ty * 4 + i;
#pragma unroll
            for (int j = 0; j < 4; j++) {
                int kj = k0 + tx * 4 + j;
                float v = sc[i][j] * scale;
                if (kj > qi) v = -1e30f;
                Ss[(ty * 4 + i) * 64 + tx * 4 + j] = v;
            }
        }
        __syncthreads();

        {
            float* row = Ss + r4 * 64 + q4 * 16;
            float mx = -1e30f;
#pragma unroll
            for (int c = 0; c < 16; c++) mx = fmaxf(mx, row[c]);
            mx = fmaxf(mx, __shfl_xor_sync(0xffffffffu, mx, 1));
            mx = fmaxf(mx, __shfl_xor_sync(0xffffffffu, mx, 2));
            float m_old = m_s[r4];
            float m_new = fmaxf(m_old, mx);
            float sum = 0.f;
#pragma unroll
            for (int c = 0; c < 16; c++) {
                float p = __expf(row[c] - m_new);
                row[c] = p;
                sum += p;
            }
            sum += __shfl_xor_sync(0xffffffffu, sum, 1);
            sum += __shfl_xor_sync(0xffffffffu, sum, 2);
            if (q4 == 0) {
                float alpha = __expf(m_old - m_new);
                m_s[r4] = m_new;
                l_s[r4] = l_s[r4] * alpha + sum;
                al_s[r4] = alpha;
            }
        }
        __syncthreads();

        float alw[4];
#pragma unroll
        for (int i = 0; i < 4; i++) alw[i] = al_s[ty * 4 + i];
#pragma unroll
        for (int i = 0; i < 4; i++)
#pragma unroll
            for (int j = 0; j < 8; j++) acc[i][j] *= alw[i];
#pragma unroll 4
        for (int kk = 0; kk < 64; kk++) {
            float p[4], vv[8];
#pragma unroll
            for (int i = 0; i < 4; i++) p[i] = Ss[(ty * 4 + i) * 64 + kk];
            *(float4*)(vv)     = *(const float4*)&Vs[kk * 128 + tx * 8];
            *(float4*)(vv + 4) = *(const float4*)&Vs[kk * 128 + tx * 8 + 4];
#pragma unroll
            for (int i = 0; i < 4; i++)
#pragma unroll
                for (int j = 0; j < 8; j++) acc[i][j] += p[i] * vv[j];
        }
    }

    float* Ob = O + (size_t)(b * Sv + q0) * NQ + h * HDv;
#pragma unroll
    for (int i = 0; i < 4; i++) {
        float inv = 1.f / l_s[ty * 4 + i];
        float* op = Ob + (size_t)(ty * 4 + i) * NQ + tx * 8;
        *(float4*)(op)     = make_float4(acc[i][0] * inv, acc[i][1] * inv,
                                         acc[i][2] * inv, acc[i][3] * inv);
        *(float4*)(op + 4) = make_float4(acc[i][4] * inv, acc[i][5] * inv,
                                         acc[i][6] * inv, acc[i][7] * inv);
    }
}

// ---------------------------------------------------------------------------
// Launch. Inputs: 0=x 1=cos 2=sin 3=positions 4=mask 5=wq 6=wk 7=wv 8=wo
// ---------------------------------------------------------------------------
extern "C" void kernel_launch(void* const* d_in, const int* in_sizes, int n_in,
                              void* d_out, int out_size)
{
    const float* x  = (const float*)d_in[0];
    const float* fc = (const float*)d_in[1];
    const float* fs = (const float*)d_in[2];
    const float* wq = (const float*)d_in[5];
    const float* wk = (const float*)d_in[6];
    const float* wv = (const float*)d_in[7];
    const float* wo = (const float*)d_in[8];
    float* out = (float*)d_out;

    float *q, *k, *v, *att;
    cudaGetSymbolAddress((void**)&q,   g_q);
    cudaGetSymbolAddress((void**)&k,   g_k);
    cudaGetSymbolAddress((void**)&v,   g_v);
    cudaGetSymbolAddress((void**)&att, g_att);
    __nv_bfloat16 *xh, *xl, *qh, *ql, *kh, *kl, *vh, *vl, *oh, *ol, *ah, *al;
    cudaGetSymbolAddress((void**)&xh, g_x_hi);  cudaGetSymbolAddress((void**)&xl, g_x_lo);
    cudaGetSymbolAddress((void**)&qh, g_wq_hi); cudaGetSymbolAddress((void**)&ql, g_wq_lo);
    cudaGetSymbolAddress((void**)&kh, g_wk_hi); cudaGetSymbolAddress((void**)&kl, g_wk_lo);
    cudaGetSymbolAddress((void**)&vh, g_wv_hi); cudaGetSymbolAddress((void**)&vl, g_wv_lo);
    cudaGetSymbolAddress((void**)&oh, g_wo_hi); cudaGetSymbolAddress((void**)&ol, g_wo_lo);
    cudaGetSymbolAddress((void**)&ah, g_at_hi); cudaGetSymbolAddress((void**)&al, g_at_lo);

    // split conversions
    {
        long n4;
        n4 = (long)Mv * Dv / 4;  cvt_split<<<(unsigned)((n4 + 255) / 256), 256>>>(x,  xh, xl, n4);
        n4 = (long)NQ * Dv / 4;  cvt_split<<<(unsigned)((n4 + 255) / 256), 256>>>(wq, qh, ql, n4);
        n4 = (long)NKV * Dv / 4; cvt_split<<<(unsigned)((n4 + 255) / 256), 256>>>(wk, kh, kl, n4);
        n4 = (long)NKV * Dv / 4; cvt_split<<<(unsigned)((n4 + 255) / 256), 256>>>(wv, vh, vl, n4);
        n4 = (long)Dv * NQ / 4;  cvt_split<<<(unsigned)((n4 + 255) / 256), 256>>>(wo, oh, ol, n4);
    }

    cudaFuncSetAttribute(gemm_hmma_x3, cudaFuncAttributeMaxDynamicSharedMemorySize, GEMM_SMEM);

    // QKV projections (HMMA bf16x3)
    gemm_hmma_x3<<<dim3(NQ / BN,  Mv / BM), 256, GEMM_SMEM>>>(xh, xl, qh, ql, q, NQ,  Dv);
    gemm_hmma_x3<<<dim3(NKV / BN, Mv / BM), 256, GEMM_SMEM>>>(xh, xl, kh, kl, k, NKV, Dv);
    gemm_hmma_x3<<<dim3(NKV / BN, Mv / BM), 256, GEMM_SMEM>>>(xh, xl, vh, vl, v, NKV, Dv);

    // RoPE
    {
        long nq_pairs = (long)Mv * Hv * (HDv / 2);
        long nk_pairs = (long)Mv * KVHv * (HDv / 2);
        rope_kernel<<<(unsigned)((nq_pairs + 255) / 256), 256>>>(q, fc, fs, Hv);
        rope_kernel<<<(unsigned)((nk_pairs + 255) / 256), 256>>>(k, fc, fs, KVHv);
    }

    // Flash attention (fp32)
    {
        const int smem_bytes = (128 * 64 + 128 * 64 + 64 * 128 + 64 * 64 + 3 * 64) * 4;
        cudaFuncSetAttribute(flash_kernel,
                             cudaFuncAttributeMaxDynamicSharedMemorySize, smem_bytes);
        flash_kernel<<<dim3(Sv / 64, Hv, Bv), 256, smem_bytes>>>(q, k, v, att);
    }

    // att -> bf16 split, then output projection
    {
        long n4 = (long)Mv * NQ / 4;
        cvt_split<<<(unsigned)((n4 + 255) / 256), 256>>>(att, ah, al, n4);
    }
    gemm_hmma_x3<<<dim3(NQ / BN, Mv / BM), 256, GEMM_SMEM>>>(ah, al, oh, ol, out, NQ, Dv);
}

// round 4
// speedup vs baseline: 3.0228x; 1.6693x over previous
#include <cuda_runtime.h>
#include <cuda_bf16.h>
#include <cstdint>
#include <math.h>

// Problem constants
#define Bv   2
#define Sv   2048
#define Dv   4096
#define Hv   32
#define KVHv 8
#define HDv  128
#define Mv   (Bv * Sv)       // 4096
#define NQ   (Hv * HDv)      // 4096
#define NKV  (KVHv * HDv)    // 1024

// fp32 scratch
__device__ float g_q[(size_t)Mv * NQ];
__device__ float g_k[(size_t)Mv * NKV];
__device__ float g_v[(size_t)Mv * NKV];
__device__ float g_att[(size_t)Mv * NQ];
// bf16 split-precision scratch (hi + lo)
__device__ __nv_bfloat16 g_x_hi[(size_t)Mv * Dv],  g_x_lo[(size_t)Mv * Dv];
__device__ __nv_bfloat16 g_wq_hi[(size_t)NQ * Dv], g_wq_lo[(size_t)NQ * Dv];
__device__ __nv_bfloat16 g_wk_hi[(size_t)NKV * Dv], g_wk_lo[(size_t)NKV * Dv];
__device__ __nv_bfloat16 g_wv_hi[(size_t)NKV * Dv], g_wv_lo[(size_t)NKV * Dv];
__device__ __nv_bfloat16 g_wo_hi[(size_t)Dv * NQ], g_wo_lo[(size_t)Dv * NQ];
__device__ __nv_bfloat16 g_at_hi[(size_t)Mv * NQ], g_at_lo[(size_t)Mv * NQ];
// rope'd / split Q,K,V for flash
__device__ __nv_bfloat16 g_qr_hi[(size_t)Mv * NQ],  g_qr_lo[(size_t)Mv * NQ];
__device__ __nv_bfloat16 g_kr_hi[(size_t)Mv * NKV], g_kr_lo[(size_t)Mv * NKV];
__device__ __nv_bfloat16 g_vs_hi[(size_t)Mv * NKV], g_vs_lo[(size_t)Mv * NKV];

// ---------------------------------------------------------------------------
// Helpers (compute_103-safe: cp.async + mma.sync + ldmatrix only)
// ---------------------------------------------------------------------------
__device__ __forceinline__ uint32_t smem_u32(const void* p) {
    uint32_t a;
    asm("{ .reg .u64 t; cvta.to.shared.u64 t, %1; cvt.u32.u64 %0, t; }" : "=r"(a) : "l"(p));
    return a;
}
__device__ __forceinline__ void cp16(uint32_t dst, const void* src) {
    asm volatile("cp.async.cg.shared.global [%0], [%1], 16;" :: "r"(dst), "l"(src));
}
#define CP_COMMIT() asm volatile("cp.async.commit_group;" ::: "memory")
#define CP_WAIT2()  asm volatile("cp.async.wait_group 2;" ::: "memory")
#define CP_WAIT0()  asm volatile("cp.async.wait_group 0;" ::: "memory")

__device__ __forceinline__ uint32_t lds32(uint32_t a) {
    uint32_t v;
    asm volatile("ld.shared.b32 %0, [%1];" : "=r"(v) : "r"(a));
    return v;
}
__device__ __forceinline__ void mma_bf16(float* c, const uint32_t* a, const uint32_t* b) {
    asm volatile("mma.sync.aligned.m16n8k16.row.col.f32.bf16.bf16.f32 "
        "{%0,%1,%2,%3}, {%4,%5,%6,%7}, {%8,%9}, {%0,%1,%2,%3};"
        : "+f"(c[0]), "+f"(c[1]), "+f"(c[2]), "+f"(c[3])
        : "r"(a[0]), "r"(a[1]), "r"(a[2]), "r"(a[3]), "r"(b[0]), "r"(b[1]));
}
__device__ __forceinline__ void ldsm_x4_t(uint32_t* r, uint32_t addr) {
    asm volatile("ldmatrix.sync.aligned.m8n8.x4.trans.shared.b16 {%0,%1,%2,%3}, [%4];"
        : "=r"(r[0]), "=r"(r[1]), "=r"(r[2]), "=r"(r[3]) : "r"(addr));
}
__device__ __forceinline__ uint32_t pack2(float x, float y) {
    __nv_bfloat162 t = __floats2bfloat162_rn(x, y);
    return *(uint32_t*)&t;
}

// ---------------------------------------------------------------------------
// Split fp32 -> bf16 hi/lo
// ---------------------------------------------------------------------------
__global__ void cvt_split(const float* __restrict__ in,
                          __nv_bfloat16* __restrict__ hi,
                          __nv_bfloat16* __restrict__ lo, long n4) {
    long i = (long)blockIdx.x * blockDim.x + threadIdx.x;
    if (i >= n4) return;
    float4 v = ((const float4*)in)[i];
    __nv_bfloat16 h[4], l[4];
    float vv[4] = {v.x, v.y, v.z, v.w};
#pragma unroll
    for (int j = 0; j < 4; j++) {
        h[j] = __float2bfloat16(vv[j]);
        l[j] = __float2bfloat16(vv[j] - __bfloat162float(h[j]));
    }
    ((__nv_bfloat162*)hi)[i * 2]     = __nv_bfloat162(h[0], h[1]);
    ((__nv_bfloat162*)hi)[i * 2 + 1] = __nv_bfloat162(h[2], h[3]);
    ((__nv_bfloat162*)lo)[i * 2]     = __nv_bfloat162(l[0], l[1]);
    ((__nv_bfloat162*)lo)[i * 2 + 1] = __nv_bfloat162(l[2], l[3]);
}

// ---------------------------------------------------------------------------
// RoPE + split: read fp32 projected tensor, apply rope, emit bf16 hi/lo.
// ---------------------------------------------------------------------------
__global__ void rope_split(const float* __restrict__ in,
                           __nv_bfloat16* __restrict__ hi,
                           __nv_bfloat16* __restrict__ lo,
                           const float* __restrict__ cs,
                           const float* __restrict__ sn, int nheads)
{
    long idx = (long)blockIdx.x * blockDim.x + threadIdx.x;
    long total = (long)Mv * nheads * (HDv / 2);
    if (idx >= total) return;
    int i = (int)(idx & 63);
    long t2 = idx >> 6;
    int h = (int)(t2 % nheads);
    int m = (int)(t2 / nheads);
    int s = m % Sv;
    float c = cs[s * 64 + i];
    float si = sn[s * 64 + i];
    size_t p = (size_t)m * (nheads * HDv) + h * HDv + 2 * i;
    float re = in[p], im = in[p + 1];
    float o_r = re * c - im * si;
    float o_i = re * si + im * c;
    __nv_bfloat16 hr = __float2bfloat16(o_r);
    __nv_bfloat16 hi_ = __float2bfloat16(o_i);
    hi[p]     = hr;
    hi[p + 1] = hi_;
    lo[p]     = __float2bfloat16(o_r - __bfloat162float(hr));
    lo[p + 1] = __float2bfloat16(o_i - __bfloat162float(hi_));
}

// ---------------------------------------------------------------------------
// HMMA bf16x3 GEMM (unchanged from R3; proven at 4.8e-5)
// ---------------------------------------------------------------------------
#define BM 128
#define BN 128
#define BK 32
#define STAGES 4
#define ROW_STRIDE 80
#define TILE_SM   (128 * ROW_STRIDE)
#define STAGE_SM  (4 * TILE_SM)
#define GEMM_SMEM (STAGES * STAGE_SM)

__device__ __forceinline__ void load_stage(
    uint32_t sbase,
    const __nv_bfloat16* __restrict__ Ahi, const __nv_bfloat16* __restrict__ Alo,
    const __nv_bfloat16* __restrict__ Bhi, const __nv_bfloat16* __restrict__ Blo,
    int m0, int n0, int k0, int K, int tid)
{
#pragma unroll
    for (int j = 0; j < 8; j++) {
        const int tile = j >> 1;
        const int cc = tid + (j & 1) * 256;
        const int row = cc >> 2;
        const int c16 = cc & 3;
        const uint32_t soff = sbase + tile * TILE_SM + row * ROW_STRIDE + c16 * 16;
        const __nv_bfloat16* g =
            (tile == 0) ? Ahi : (tile == 1) ? Alo : (tile == 2) ? Bhi : Blo;
        const int grow = (tile < 2) ? (m0 + row) : (n0 + row);
        cp16(soff, g + (size_t)grow * K + k0 + c16 * 8);
    }
}

__global__ __launch_bounds__(256) void gemm_hmma_x3(
    const __nv_bfloat16* __restrict__ Ahi, const __nv_bfloat16* __restrict__ Alo,
    const __nv_bfloat16* __restrict__ Bhi, const __nv_bfloat16* __restrict__ Blo,
    float* __restrict__ C, int N, int K)
{
    extern __shared__ char smem[];
    const uint32_t sb = smem_u32(smem);
    const int tid = threadIdx.x;
    const int wid = tid >> 5, lane = tid & 31;
    const int wm = wid & 1;
    const int wn = wid >> 1;
    const int lr = lane >> 2;
    const int lc4 = (lane & 3) * 4;
    const int m0 = blockIdx.y * BM, n0 = blockIdx.x * BN;

    float acc[4][4][4];
#pragma unroll
    for (int mt = 0; mt < 4; mt++)
#pragma unroll
        for (int nt = 0; nt < 4; nt++)
#pragma unroll
            for (int r = 0; r < 4; r++) acc[mt][nt][r] = 0.f;

    const int NIT = K / BK;

#pragma unroll
    for (int p = 0; p < STAGES - 1; p++) {
        load_stage(sb + p * STAGE_SM, Ahi, Alo, Bhi, Blo, m0, n0, p * BK, K, tid);
        CP_COMMIT();
    }

    for (int it = 0; it < NIT; ++it) {
        CP_WAIT2();
        __syncthreads();

        const int pre = it + STAGES - 1;
        if (pre < NIT)
            load_stage(sb + (pre % STAGES) * STAGE_SM,
                       Ahi, Alo, Bhi, Blo, m0, n0, pre * BK, K, tid);
        CP_COMMIT();

        const uint32_t sA = sb + (it % STAGES) * STAGE_SM;
        const uint32_t sB = sA + 2 * TILE_SM;
#pragma unroll
        for (int kk = 0; kk < 2; kk++) {
            uint32_t ah[4][4], al[4][4], bh[4][2], bl[4][2];
#pragma unroll
            for (int mt = 0; mt < 4; mt++) {
                uint32_t base = sA + (wm * 64 + mt * 16 + lr) * ROW_STRIDE + kk * 32 + lc4;
                ah[mt][0] = lds32(base);
                ah[mt][1] = lds32(base + 8 * ROW_STRIDE);
                ah[mt][2] = lds32(base + 16);
                ah[mt][3] = lds32(base + 8 * ROW_STRIDE + 16);
                base += TILE_SM;
                al[mt][0] = lds32(base);
                al[mt][1] = lds32(base + 8 * ROW_STRIDE);
                al[mt][2] = lds32(base + 16);
                al[mt][3] = lds32(base + 8 * ROW_STRIDE + 16);
            }
#pragma unroll
            for (int nt = 0; nt < 4; nt++) {
                uint32_t base = sB + (wn * 32 + nt * 8 + lr) * ROW_STRIDE + kk * 32 + lc4;
                bh[nt][0] = lds32(base);
                bh[nt][1] = lds32(base + 16);
                base += TILE_SM;
                bl[nt][0] = lds32(base);
                bl[nt][1] = lds32(base + 16);
            }
#pragma unroll
            for (int mt = 0; mt < 4; mt++)
#pragma unroll
                for (int nt = 0; nt < 4; nt++) {
                    mma_bf16(acc[mt][nt], ah[mt], bh[nt]);
                    mma_bf16(acc[mt][nt], ah[mt], bl[nt]);
                    mma_bf16(acc[mt][nt], al[mt], bh[nt]);
                }
        }
    }

#pragma unroll
    for (int mt = 0; mt < 4; mt++) {
        const int row = m0 + wm * 64 + mt * 16 + lr;
#pragma unroll
        for (int nt = 0; nt < 4; nt++) {
            const int col = n0 + wn * 32 + nt * 8 + (lane & 3) * 2;
            float2* p0 = (float2*)&C[(size_t)row * N + col];
            float2* p1 = (float2*)&C[(size_t)(row + 8) * N + col];
            *p0 = make_float2(acc[mt][nt][0], acc[mt][nt][1]);
            *p1 = make_float2(acc[mt][nt][2], acc[mt][nt][3]);
        }
    }
}

// ---------------------------------------------------------------------------
// HMMA flash attention (split-bf16 x3 for both QK^T and PV).
// CTA: 128 q-rows x (head) x (batch), 8 warps, 16 q-rows/warp, d=128.
// K/V tiles of 64 double-buffered via cp.async. Q staged once.
// smem rows: 128 bf16 = 256B + 16B pad = 272B (conflict-free for lds32
// fragment pattern and for ldmatrix 8-row phases).
// ---------------------------------------------------------------------------
#define FROWB 272
#define FQ_HALF (128 * FROWB)      // 34816
#define FK_HALF (64 * FROWB)       // 17408
#define SM_K0   (2 * FQ_HALF)      // 69632
#define SM_V0   (SM_K0 + 4 * FK_HALF)  // 139264
#define FLASH_SMEM (SM_V0 + 4 * FK_HALF)  // 208896

__device__ __forceinline__ void flash_load_kv(
    uint32_t sb, int stage,
    const __nv_bfloat16* __restrict__ Kh, const __nv_bfloat16* __restrict__ Kl,
    const __nv_bfloat16* __restrict__ Vh, const __nv_bfloat16* __restrict__ Vl,
    size_t gbase, int tid)
{
#pragma unroll
    for (int j = 0; j < 16; j++) {
        const int t = j >> 2;                 // 0:Kh 1:Kl 2:Vh 3:Vl
        const int cc = tid + (j & 3) * 256;   // 0..1023
        const int row = cc >> 4, c16 = cc & 15;
        const __nv_bfloat16* g = (t == 0) ? Kh : (t == 1) ? Kl : (t == 2) ? Vh : Vl;
        const uint32_t soff = sb + ((t < 2) ? SM_K0 : SM_V0) + stage * 2 * FK_HALF
                              + (t & 1) * FK_HALF + row * FROWB + c16 * 16;
        cp16(soff, g + gbase + (size_t)row * NKV + c16 * 8);
    }
}

__global__ __launch_bounds__(256, 1) void flash_hmma(
    const __nv_bfloat16* __restrict__ Qh_g, const __nv_bfloat16* __restrict__ Ql_g,
    const __nv_bfloat16* __restrict__ Kh_g, const __nv_bfloat16* __restrict__ Kl_g,
    const __nv_bfloat16* __restrict__ Vh_g, const __nv_bfloat16* __restrict__ Vl_g,
    float* __restrict__ O)
{
    extern __shared__ char smem[];
    const uint32_t sb = smem_u32(smem);
    const int tid = threadIdx.x, w = tid >> 5, lane = tid & 31;
    const int lr = lane >> 2, lc = lane & 3;
    const int q0 = blockIdx.x * 128, h = blockIdx.y, b = blockIdx.z;
    const int kvh = h >> 2;                 // H/KVH = 4
    const float scale = 0.08838834764831845f;

    // Stage Q (hi/lo) once
    {
        const size_t gq = ((size_t)(b * Sv + q0)) * NQ + h * HDv;
#pragma unroll
        for (int j = 0; j < 16; j++) {
            const int hl = j >> 3;
            const int cc = tid + (j & 7) * 256;   // 0..2047
            const int row = cc >> 4, c16 = cc & 15;
            const __nv_bfloat16* g = hl ? Ql_g : Qh_g;
            cp16(sb + hl * FQ_HALF + row * FROWB + c16 * 16,
                 g + gq + (size_t)row * NQ + c16 * 8);
        }
    }
    // First K/V tile
    const int ktmax = 2 * blockIdx.x + 1;
    flash_load_kv(sb, 0, Kh_g, Kl_g, Vh_g, Vl_g,
                  ((size_t)(b * Sv)) * NKV + kvh * HDv, tid);
    CP_COMMIT();

    float o[16][4];
#pragma unroll
    for (int i = 0; i < 16; i++)
#pragma unroll
        for (int j = 0; j < 4; j++) o[i][j] = 0.f;
    float mrow[2] = {-1e30f, -1e30f};
    float lrow[2] = {0.f, 0.f};

    for (int kt = 0; kt <= ktmax; ++kt) {
        CP_WAIT0();
        __syncthreads();
        if (kt < ktmax) {
            flash_load_kv(sb, (kt + 1) & 1, Kh_g, Kl_g, Vh_g, Vl_g,
                          ((size_t)(b * Sv + (kt + 1) * 64)) * NKV + kvh * HDv, tid);
            CP_COMMIT();
        }

        const int k0 = kt * 64;
        if (k0 > q0 + w * 16 + 15) continue;   // fully masked for this warp

        const uint32_t Kst = sb + SM_K0 + (kt & 1) * 2 * FK_HALF;
        const uint32_t Vst = sb + SM_V0 + (kt & 1) * 2 * FK_HALF;

        // ---- S = Q K^T (3-pass split) ----
        float s[8][4];
#pragma unroll
        for (int nf = 0; nf < 8; nf++)
#pragma unroll
            for (int r = 0; r < 4; r++) s[nf][r] = 0.f;

#pragma unroll
        for (int kf = 0; kf < 8; kf++) {
            uint32_t qb = sb + (w * 16 + lr) * FROWB + kf * 32 + lc * 4;
            uint32_t ah[4], al[4];
            ah[0] = lds32(qb);
            ah[1] = lds32(qb + 8 * FROWB);
            ah[2] = lds32(qb + 16);
            ah[3] = lds32(qb + 8 * FROWB + 16);
            qb += FQ_HALF;
            al[0] = lds32(qb);
            al[1] = lds32(qb + 8 * FROWB);
            al[2] = lds32(qb + 16);
            al[3] = lds32(qb + 8 * FROWB + 16);
#pragma unroll
            for (int nf = 0; nf < 8; nf++) {
                uint32_t kb = Kst + (nf * 8 + lr) * FROWB + kf * 32 + lc * 4;
                uint32_t bh[2], bl[2];
                bh[0] = lds32(kb);
                bh[1] = lds32(kb + 16);
                bl[0] = lds32(kb + FK_HALF);
                bl[1] = lds32(kb + FK_HALF + 16);
                mma_bf16(s[nf], ah, bh);
                mma_bf16(s[nf], ah, bl);
                mma_bf16(s[nf], al, bh);
            }
        }

        // ---- scale + causal mask + online softmax ----
        const bool diag = (k0 + 63 > q0 + w * 16);
#pragma unroll
        for (int r = 0; r < 2; r++) {
            const int qrow = q0 + w * 16 + lr + 8 * r;
            float mx = -1e30f;
#pragma unroll
            for (int nf = 0; nf < 8; nf++) {
                float v0 = s[nf][2 * r] * scale;
                float v1 = s[nf][2 * r + 1] * scale;
                if (diag) {
                    const int col = k0 + nf * 8 + lc * 2;
                    if (col > qrow) v0 = -1e30f;
                    if (col + 1 > qrow) v1 = -1e30f;
                }
                s[nf][2 * r] = v0;
                s[nf][2 * r + 1] = v1;
                mx = fmaxf(mx, fmaxf(v0, v1));
            }
            mx = fmaxf(mx, __shfl_xor_sync(0xffffffffu, mx, 1));
            mx = fmaxf(mx, __shfl_xor_sync(0xffffffffu, mx, 2));
            const float m_new = fmaxf(mrow[r], mx);
            const float alpha = __expf(mrow[r] - m_new);
            mrow[r] = m_new;
            float sum = 0.f;
#pragma unroll
            for (int nf = 0; nf < 8; nf++) {
                float p0 = __expf(s[nf][2 * r] - m_new);
                float p1 = __expf(s[nf][2 * r + 1] - m_new);
                s[nf][2 * r] = p0;
                s[nf][2 * r + 1] = p1;
                sum += p0 + p1;
            }
            sum += __shfl_xor_sync(0xffffffffu, sum, 1);
            sum += __shfl_xor_sync(0xffffffffu, sum, 2);
            lrow[r] = lrow[r] * alpha + sum;
#pragma unroll
            for (int nf2 = 0; nf2 < 16; nf2++) {
                o[nf2][2 * r] *= alpha;
                o[nf2][2 * r + 1] *= alpha;
            }
        }

        // ---- split P into hi/lo A-fragments (register-only) ----
        uint32_t phi[4][4], plo[4][4];
#pragma unroll
        for (int kf2 = 0; kf2 < 4; kf2++) {
#pragma unroll
            for (int m = 0; m < 2; m++) {
                const int nf = 2 * kf2 + m;
                float x0 = s[nf][0], x1 = s[nf][1], x2 = s[nf][2], x3 = s[nf][3];
                uint32_t h01 = pack2(x0, x1), h23 = pack2(x2, x3);
                phi[kf2][2 * m]     = h01;
                phi[kf2][2 * m + 1] = h23;
                __nv_bfloat162 b01 = *(__nv_bfloat162*)&h01;
                __nv_bfloat162 b23 = *(__nv_bfloat162*)&h23;
                plo[kf2][2 * m]     = pack2(x0 - __bfloat162float(b01.x),
                                            x1 - __bfloat162float(b01.y));
                plo[kf2][2 * m + 1] = pack2(x2 - __bfloat162float(b23.x),
                                            x3 - __bfloat162float(b23.y));
            }
        }

        // ---- O += P V (3-pass split), V fragments via ldmatrix.trans ----
#pragma unroll
        for (int kf2 = 0; kf2 < 4; kf2++) {
#pragma unroll
            for (int nfp = 0; nfp < 8; nfp++) {
                const uint32_t va = Vst + (kf2 * 16 + (lane & 15)) * FROWB
                                    + (nfp * 16 + ((lane >> 4) << 3)) * 2;
                uint32_t bh4[4], bl4[4];
                ldsm_x4_t(bh4, va);
                ldsm_x4_t(bl4, va + FK_HALF);
                mma_bf16(o[2 * nfp],     phi[kf2], bh4);
                mma_bf16(o[2 * nfp],     phi[kf2], bl4);
                mma_bf16(o[2 * nfp],     plo[kf2], bh4);
                mma_bf16(o[2 * nfp + 1], phi[kf2], bh4 + 2);
                mma_bf16(o[2 * nfp + 1], phi[kf2], bl4 + 2);
                mma_bf16(o[2 * nfp + 1], plo[kf2], bh4 + 2);
            }
        }
    }

    // ---- epilogue ----
#pragma unroll
    for (int r = 0; r < 2; r++) {
        const float inv = 1.f / lrow[r];
        const int row = q0 + w * 16 + lr + 8 * r;
        float* Ob = O + ((size_t)(b * Sv + row)) * NQ + h * HDv + lc * 2;
#pragma unroll
        for (int nf2 = 0; nf2 < 16; nf2++) {
            *(float2*)(Ob + nf2 * 8) =
                make_float2(o[nf2][2 * r] * inv, o[nf2][2 * r + 1] * inv);
        }
    }
}

// ---------------------------------------------------------------------------
// Launch. Inputs: 0=x 1=cos 2=sin 3=positions 4=mask 5=wq 6=wk 7=wv 8=wo
// ---------------------------------------------------------------------------
extern "C" void kernel_launch(void* const* d_in, const int* in_sizes, int n_in,
                              void* d_out, int out_size)
{
    const float* x  = (const float*)d_in[0];
    const float* fc = (const float*)d_in[1];
    const float* fs = (const float*)d_in[2];
    const float* wq = (const float*)d_in[5];
    const float* wk = (const float*)d_in[6];
    const float* wv = (const float*)d_in[7];
    const float* wo = (const float*)d_in[8];
    float* out = (float*)d_out;

    float *q, *k, *v, *att;
    cudaGetSymbolAddress((void**)&q,   g_q);
    cudaGetSymbolAddress((void**)&k,   g_k);
    cudaGetSymbolAddress((void**)&v,   g_v);
    cudaGetSymbolAddress((void**)&att, g_att);
    __nv_bfloat16 *xh, *xl, *qh, *ql, *kh, *kl, *vh, *vl, *oh, *ol, *ah, *al;
    __nv_bfloat16 *qrh, *qrl, *krh, *krl, *vsh, *vsl;
    cudaGetSymbolAddress((void**)&xh, g_x_hi);  cudaGetSymbolAddress((void**)&xl, g_x_lo);
    cudaGetSymbolAddress((void**)&qh, g_wq_hi); cudaGetSymbolAddress((void**)&ql, g_wq_lo);
    cudaGetSymbolAddress((void**)&kh, g_wk_hi); cudaGetSymbolAddress((void**)&kl, g_wk_lo);
    cudaGetSymbolAddress((void**)&vh, g_wv_hi); cudaGetSymbolAddress((void**)&vl, g_wv_lo);
    cudaGetSymbolAddress((void**)&oh, g_wo_hi); cudaGetSymbolAddress((void**)&ol, g_wo_lo);
    cudaGetSymbolAddress((void**)&ah, g_at_hi); cudaGetSymbolAddress((void**)&al, g_at_lo);
    cudaGetSymbolAddress((void**)&qrh, g_qr_hi); cudaGetSymbolAddress((void**)&qrl, g_qr_lo);
    cudaGetSymbolAddress((void**)&krh, g_kr_hi); cudaGetSymbolAddress((void**)&krl, g_kr_lo);
    cudaGetSymbolAddress((void**)&vsh, g_vs_hi); cudaGetSymbolAddress((void**)&vsl, g_vs_lo);

    // split conversions for projections
    {
        long n4;
        n4 = (long)Mv * Dv / 4;  cvt_split<<<(unsigned)((n4 + 255) / 256), 256>>>(x,  xh, xl, n4);
        n4 = (long)NQ * Dv / 4;  cvt_split<<<(unsigned)((n4 + 255) / 256), 256>>>(wq, qh, ql, n4);
        n4 = (long)NKV * Dv / 4; cvt_split<<<(unsigned)((n4 + 255) / 256), 256>>>(wk, kh, kl, n4);
        n4 = (long)NKV * Dv / 4; cvt_split<<<(unsigned)((n4 + 255) / 256), 256>>>(wv, vh, vl, n4);
        n4 = (long)Dv * NQ / 4;  cvt_split<<<(unsigned)((n4 + 255) / 256), 256>>>(wo, oh, ol, n4);
    }

    cudaFuncSetAttribute(gemm_hmma_x3, cudaFuncAttributeMaxDynamicSharedMemorySize, GEMM_SMEM);

    // QKV projections
    gemm_hmma_x3<<<dim3(NQ / BN,  Mv / BM), 256, GEMM_SMEM>>>(xh, xl, qh, ql, q, NQ,  Dv);
    gemm_hmma_x3<<<dim3(NKV / BN, Mv / BM), 256, GEMM_SMEM>>>(xh, xl, kh, kl, k, NKV, Dv);
    gemm_hmma_x3<<<dim3(NKV / BN, Mv / BM), 256, GEMM_SMEM>>>(xh, xl, vh, vl, v, NKV, Dv);

    // RoPE + split for Q,K; split for V
    {
        long nq_pairs = (long)Mv * Hv * (HDv / 2);
        long nk_pairs = (long)Mv * KVHv * (HDv / 2);
        rope_split<<<(unsigned)((nq_pairs + 255) / 256), 256>>>(q, qrh, qrl, fc, fs, Hv);
        rope_split<<<(unsigned)((nk_pairs + 255) / 256), 256>>>(k, krh, krl, fc, fs, KVHv);
        long n4 = (long)Mv * NKV / 4;
        cvt_split<<<(unsigned)((n4 + 255) / 256), 256>>>(v, vsh, vsl, n4);
    }

    // HMMA flash attention
    cudaFuncSetAttribute(flash_hmma, cudaFuncAttributeMaxDynamicSharedMemorySize, FLASH_SMEM);
    flash_hmma<<<dim3(Sv / 128, Hv, Bv), 256, FLASH_SMEM>>>(
        qrh, qrl, krh, krl, vsh, vsl, att);

    // att -> split, output projection
    {
        long n4 = (long)Mv * NQ / 4;
        cvt_split<<<(unsigned)((n4 + 255) / 256), 256>>>(att, ah, al, n4);
    }
    gemm_hmma_x3<<<dim3(NQ / BN, Mv / BM), 256, GEMM_SMEM>>>(ah, al, oh, ol, out, NQ, Dv);
}

// round 5
// speedup vs baseline: 3.1532x; 1.0432x over previous
#include <cuda_runtime.h>
#include <cuda_bf16.h>
#include <cstdint>
#include <math.h>

// Problem constants
#define Bv   2
#define Sv   2048
#define Dv   4096
#define Hv   32
#define KVHv 8
#define HDv  128
#define Mv   (Bv * Sv)       // 4096
#define NQ   (Hv * HDv)      // 4096
#define NKV  (KVHv * HDv)    // 1024

// fp32 scratch
__device__ float g_q[(size_t)Mv * NQ];
__device__ float g_k[(size_t)Mv * NKV];
__device__ float g_v[(size_t)Mv * NKV];
// bf16 split-precision scratch (hi + lo)
__device__ __nv_bfloat16 g_x_hi[(size_t)Mv * Dv],  g_x_lo[(size_t)Mv * Dv];
__device__ __nv_bfloat16 g_wq_hi[(size_t)NQ * Dv], g_wq_lo[(size_t)NQ * Dv];
__device__ __nv_bfloat16 g_wk_hi[(size_t)NKV * Dv], g_wk_lo[(size_t)NKV * Dv];
__device__ __nv_bfloat16 g_wv_hi[(size_t)NKV * Dv], g_wv_lo[(size_t)NKV * Dv];
__device__ __nv_bfloat16 g_wo_hi[(size_t)Dv * NQ], g_wo_lo[(size_t)Dv * NQ];
__device__ __nv_bfloat16 g_at_hi[(size_t)Mv * NQ], g_at_lo[(size_t)Mv * NQ];
// rope'd / split Q,K,V for flash
__device__ __nv_bfloat16 g_qr_hi[(size_t)Mv * NQ],  g_qr_lo[(size_t)Mv * NQ];
__device__ __nv_bfloat16 g_kr_hi[(size_t)Mv * NKV], g_kr_lo[(size_t)Mv * NKV];
__device__ __nv_bfloat16 g_vs_hi[(size_t)Mv * NKV], g_vs_lo[(size_t)Mv * NKV];

// ---------------------------------------------------------------------------
// Helpers (compute_103-safe: cp.async + mma.sync + ldmatrix only)
// ---------------------------------------------------------------------------
__device__ __forceinline__ uint32_t smem_u32(const void* p) {
    uint32_t a;
    asm("{ .reg .u64 t; cvta.to.shared.u64 t, %1; cvt.u32.u64 %0, t; }" : "=r"(a) : "l"(p));
    return a;
}
__device__ __forceinline__ void cp16(uint32_t dst, const void* src) {
    asm volatile("cp.async.cg.shared.global [%0], [%1], 16;" :: "r"(dst), "l"(src));
}
#define CP_COMMIT() asm volatile("cp.async.commit_group;" ::: "memory")
#define CP_WAIT2()  asm volatile("cp.async.wait_group 2;" ::: "memory")
#define CP_WAIT0()  asm volatile("cp.async.wait_group 0;" ::: "memory")

__device__ __forceinline__ void mma_bf16(float* c, const uint32_t* a, const uint32_t* b) {
    asm volatile("mma.sync.aligned.m16n8k16.row.col.f32.bf16.bf16.f32 "
        "{%0,%1,%2,%3}, {%4,%5,%6,%7}, {%8,%9}, {%0,%1,%2,%3};"
        : "+f"(c[0]), "+f"(c[1]), "+f"(c[2]), "+f"(c[3])
        : "r"(a[0]), "r"(a[1]), "r"(a[2]), "r"(a[3]), "r"(b[0]), "r"(b[1]));
}
__device__ __forceinline__ void ldsm_x4(uint32_t* r, uint32_t addr) {
    asm volatile("ldmatrix.sync.aligned.m8n8.x4.shared.b16 {%0,%1,%2,%3}, [%4];"
        : "=r"(r[0]), "=r"(r[1]), "=r"(r[2]), "=r"(r[3]) : "r"(addr));
}
__device__ __forceinline__ void ldsm_x4_t(uint32_t* r, uint32_t addr) {
    asm volatile("ldmatrix.sync.aligned.m8n8.x4.trans.shared.b16 {%0,%1,%2,%3}, [%4];"
        : "=r"(r[0]), "=r"(r[1]), "=r"(r[2]), "=r"(r[3]) : "r"(addr));
}
__device__ __forceinline__ uint32_t pack2(float x, float y) {
    __nv_bfloat162 t = __floats2bfloat162_rn(x, y);
    return *(uint32_t*)&t;
}

// ---------------------------------------------------------------------------
// Split fp32 -> bf16 hi/lo
// ---------------------------------------------------------------------------
__global__ void cvt_split(const float* __restrict__ in,
                          __nv_bfloat16* __restrict__ hi,
                          __nv_bfloat16* __restrict__ lo, long n4) {
    long i = (long)blockIdx.x * blockDim.x + threadIdx.x;
    if (i >= n4) return;
    float4 v = ((const float4*)in)[i];
    __nv_bfloat16 h[4], l[4];
    float vv[4] = {v.x, v.y, v.z, v.w};
#pragma unroll
    for (int j = 0; j < 4; j++) {
        h[j] = __float2bfloat16(vv[j]);
        l[j] = __float2bfloat16(vv[j] - __bfloat162float(h[j]));
    }
    ((__nv_bfloat162*)hi)[i * 2]     = __nv_bfloat162(h[0], h[1]);
    ((__nv_bfloat162*)hi)[i * 2 + 1] = __nv_bfloat162(h[2], h[3]);
    ((__nv_bfloat162*)lo)[i * 2]     = __nv_bfloat162(l[0], l[1]);
    ((__nv_bfloat162*)lo)[i * 2 + 1] = __nv_bfloat162(l[2], l[3]);
}

// ---------------------------------------------------------------------------
// RoPE + split: read fp32 projected tensor, apply rope, emit bf16 hi/lo.
// ---------------------------------------------------------------------------
__global__ void rope_split(const float* __restrict__ in,
                           __nv_bfloat16* __restrict__ hi,
                           __nv_bfloat16* __restrict__ lo,
                           const float* __restrict__ cs,
                           const float* __restrict__ sn, int nheads)
{
    long idx = (long)blockIdx.x * blockDim.x + threadIdx.x;
    long total = (long)Mv * nheads * (HDv / 2);
    if (idx >= total) return;
    int i = (int)(idx & 63);
    long t2 = idx >> 6;
    int h = (int)(t2 % nheads);
    int m = (int)(t2 / nheads);
    int s = m % Sv;
    float c = cs[s * 64 + i];
    float si = sn[s * 64 + i];
    size_t p = (size_t)m * (nheads * HDv) + h * HDv + 2 * i;
    float re = in[p], im = in[p + 1];
    float o_r = re * c - im * si;
    float o_i = re * si + im * c;
    __nv_bfloat16 hr = __float2bfloat16(o_r);
    __nv_bfloat16 hi_ = __float2bfloat16(o_i);
    hi[p]     = hr;
    hi[p + 1] = hi_;
    lo[p]     = __float2bfloat16(o_r - __bfloat162float(hr));
    lo[p + 1] = __float2bfloat16(o_i - __bfloat162float(hi_));
}

// ---------------------------------------------------------------------------
// HMMA bf16x3 GEMM with ldmatrix fragment loads.
// 128x128 CTA tile, BK=32, 4-stage cp.async pipeline, 8 warps (64x32 each).
// 80B smem row stride: 8-row groups hit disjoint bank quads (20r mod 32)
// -> every ldmatrix phase conflict-free.
// ---------------------------------------------------------------------------
#define BM 128
#define BN 128
#define BK 32
#define STAGES 4
#define ROW_STRIDE 80
#define TILE_SM   (128 * ROW_STRIDE)
#define STAGE_SM  (4 * TILE_SM)
#define GEMM_SMEM (STAGES * STAGE_SM)

__device__ __forceinline__ void load_stage(
    uint32_t sbase,
    const __nv_bfloat16* __restrict__ Ahi, const __nv_bfloat16* __restrict__ Alo,
    const __nv_bfloat16* __restrict__ Bhi, const __nv_bfloat16* __restrict__ Blo,
    int m0, int n0, int k0, int K, int tid)
{
#pragma unroll
    for (int j = 0; j < 8; j++) {
        const int tile = j >> 1;
        const int cc = tid + (j & 1) * 256;
        const int row = cc >> 2;
        const int c16 = cc & 3;
        const uint32_t soff = sbase + tile * TILE_SM + row * ROW_STRIDE + c16 * 16;
        const __nv_bfloat16* g =
            (tile == 0) ? Ahi : (tile == 1) ? Alo : (tile == 2) ? Bhi : Blo;
        const int grow = (tile < 2) ? (m0 + row) : (n0 + row);
        cp16(soff, g + (size_t)grow * K + k0 + c16 * 8);
    }
}

__global__ __launch_bounds__(256) void gemm_hmma_x3(
    const __nv_bfloat16* __restrict__ Ahi, const __nv_bfloat16* __restrict__ Alo,
    const __nv_bfloat16* __restrict__ Bhi, const __nv_bfloat16* __restrict__ Blo,
    float* __restrict__ C, int N, int K)
{
    extern __shared__ char smem[];
    const uint32_t sb = smem_u32(smem);
    const int tid = threadIdx.x;
    const int wid = tid >> 5, lane = tid & 31;
    const int wm = wid & 1;
    const int wn = wid >> 1;
    const int lr = lane >> 2;
    const int m0 = blockIdx.y * BM, n0 = blockIdx.x * BN;

    float acc[4][4][4];
#pragma unroll
    for (int mt = 0; mt < 4; mt++)
#pragma unroll
        for (int nt = 0; nt < 4; nt++)
#pragma unroll
            for (int r = 0; r < 4; r++) acc[mt][nt][r] = 0.f;

    const int NIT = K / BK;

#pragma unroll
    for (int p = 0; p < STAGES - 1; p++) {
        load_stage(sb + p * STAGE_SM, Ahi, Alo, Bhi, Blo, m0, n0, p * BK, K, tid);
        CP_COMMIT();
    }

    // ldmatrix address components (row part within a 16-row fragment)
    const int a_row = lane & 15;            // A: lanes 0-15 rows, 16-31 rows (+16B col)
    const int a_cb  = (lane >> 4) << 4;
    const int b_row = (lane & 7) + ((lane >> 4) << 3);   // B: two 8-row n-tiles
    const int b_cb  = ((lane >> 3) & 1) << 4;

    for (int it = 0; it < NIT; ++it) {
        CP_WAIT2();
        __syncthreads();

        const int pre = it + STAGES - 1;
        if (pre < NIT)
            load_stage(sb + (pre % STAGES) * STAGE_SM,
                       Ahi, Alo, Bhi, Blo, m0, n0, pre * BK, K, tid);
        CP_COMMIT();

        const uint32_t sA = sb + (it % STAGES) * STAGE_SM;
        const uint32_t sB = sA + 2 * TILE_SM;
#pragma unroll
        for (int kk = 0; kk < 2; kk++) {
            uint32_t ah[4][4], al[4][4], bh[2][4], bl[2][4];
#pragma unroll
            for (int mt = 0; mt < 4; mt++) {
                const uint32_t aaddr = sA + (wm * 64 + mt * 16 + a_row) * ROW_STRIDE
                                       + kk * 32 + a_cb;
                ldsm_x4(ah[mt], aaddr);
                ldsm_x4(al[mt], aaddr + TILE_SM);
            }
#pragma unroll
            for (int ntp = 0; ntp < 2; ntp++) {
                const uint32_t baddr = sB + (wn * 32 + ntp * 16 + b_row) * ROW_STRIDE
                                       + kk * 32 + b_cb;
                ldsm_x4(bh[ntp], baddr);
                ldsm_x4(bl[ntp], baddr + TILE_SM);
            }
#pragma unroll
            for (int mt = 0; mt < 4; mt++)
#pragma unroll
                for (int nt = 0; nt < 4; nt++) {
                    const uint32_t* bhf = bh[nt >> 1] + (nt & 1) * 2;
                    const uint32_t* blf = bl[nt >> 1] + (nt & 1) * 2;
                    mma_bf16(acc[mt][nt], ah[mt], bhf);
                    mma_bf16(acc[mt][nt], ah[mt], blf);
                    mma_bf16(acc[mt][nt], al[mt], bhf);
                }
        }
    }

#pragma unroll
    for (int mt = 0; mt < 4; mt++) {
        const int row = m0 + wm * 64 + mt * 16 + lr;
#pragma unroll
        for (int nt = 0; nt < 4; nt++) {
            const int col = n0 + wn * 32 + nt * 8 + (lane & 3) * 2;
            float2* p0 = (float2*)&C[(size_t)row * N + col];
            float2* p1 = (float2*)&C[(size_t)(row + 8) * N + col];
            *p0 = make_float2(acc[mt][nt][0], acc[mt][nt][1]);
            *p1 = make_float2(acc[mt][nt][2], acc[mt][nt][3]);
        }
    }
}

// ---------------------------------------------------------------------------
// HMMA flash attention (split-bf16 x3, ldmatrix fragment loads).
// CTA: 128 q-rows x (head) x (batch), 8 warps, 16 q-rows/warp, d=128.
// Writes attention output directly as split bf16 hi/lo.
// ---------------------------------------------------------------------------
#define FROWB 272
#define FQ_HALF (128 * FROWB)
#define FK_HALF (64 * FROWB)
#define SM_K0   (2 * FQ_HALF)
#define SM_V0   (SM_K0 + 4 * FK_HALF)
#define FLASH_SMEM (SM_V0 + 4 * FK_HALF)

__device__ __forceinline__ void flash_load_kv(
    uint32_t sb, int stage,
    const __nv_bfloat16* __restrict__ Kh, const __nv_bfloat16* __restrict__ Kl,
    const __nv_bfloat16* __restrict__ Vh, const __nv_bfloat16* __restrict__ Vl,
    size_t gbase, int tid)
{
#pragma unroll
    for (int j = 0; j < 16; j++) {
        const int t = j >> 2;
        const int cc = tid + (j & 3) * 256;
        const int row = cc >> 4, c16 = cc & 15;
        const __nv_bfloat16* g = (t == 0) ? Kh : (t == 1) ? Kl : (t == 2) ? Vh : Vl;
        const uint32_t soff = sb + ((t < 2) ? SM_K0 : SM_V0) + stage * 2 * FK_HALF
                              + (t & 1) * FK_HALF + row * FROWB + c16 * 16;
        cp16(soff, g + gbase + (size_t)row * NKV + c16 * 8);
    }
}

__global__ __launch_bounds__(256, 1) void flash_hmma(
    const __nv_bfloat16* __restrict__ Qh_g, const __nv_bfloat16* __restrict__ Ql_g,
    const __nv_bfloat16* __restrict__ Kh_g, const __nv_bfloat16* __restrict__ Kl_g,
    const __nv_bfloat16* __restrict__ Vh_g, const __nv_bfloat16* __restrict__ Vl_g,
    __nv_bfloat16* __restrict__ Oh, __nv_bfloat16* __restrict__ Ol)
{
    extern __shared__ char smem[];
    const uint32_t sb = smem_u32(smem);
    const int tid = threadIdx.x, w = tid >> 5, lane = tid & 31;
    const int lr = lane >> 2, lc = lane & 3;
    const int q0 = blockIdx.x * 128, h = blockIdx.y, b = blockIdx.z;
    const int kvh = h >> 2;
    const float scale = 0.08838834764831845f;

    // Stage Q (hi/lo) once
    {
        const size_t gq = ((size_t)(b * Sv + q0)) * NQ + h * HDv;
#pragma unroll
        for (int j = 0; j < 16; j++) {
            const int hl = j >> 3;
            const int cc = tid + (j & 7) * 256;
            const int row = cc >> 4, c16 = cc & 15;
            const __nv_bfloat16* g = hl ? Ql_g : Qh_g;
            cp16(sb + hl * FQ_HALF + row * FROWB + c16 * 16,
                 g + gq + (size_t)row * NQ + c16 * 8);
        }
    }
    const int ktmax = 2 * blockIdx.x + 1;
    flash_load_kv(sb, 0, Kh_g, Kl_g, Vh_g, Vl_g,
                  ((size_t)(b * Sv)) * NKV + kvh * HDv, tid);
    CP_COMMIT();

    float o[16][4];
#pragma unroll
    for (int i = 0; i < 16; i++)
#pragma unroll
        for (int j = 0; j < 4; j++) o[i][j] = 0.f;
    float mrow[2] = {-1e30f, -1e30f};
    float lrow[2] = {0.f, 0.f};

    // ldmatrix address components
    const int a_row = lane & 15;
    const int a_cb  = (lane >> 4) << 4;
    const int b_row = (lane & 7) + ((lane >> 4) << 3);
    const int b_cb  = ((lane >> 3) & 1) << 4;

    for (int kt = 0; kt <= ktmax; ++kt) {
        CP_WAIT0();
        __syncthreads();
        if (kt < ktmax) {
            flash_load_kv(sb, (kt + 1) & 1, Kh_g, Kl_g, Vh_g, Vl_g,
                          ((size_t)(b * Sv + (kt + 1) * 64)) * NKV + kvh * HDv, tid);
            CP_COMMIT();
        }

        const int k0 = kt * 64;
        if (k0 > q0 + w * 16 + 15) continue;

        const uint32_t Kst = sb + SM_K0 + (kt & 1) * 2 * FK_HALF;
        const uint32_t Vst = sb + SM_V0 + (kt & 1) * 2 * FK_HALF;

        // ---- S = Q K^T (3-pass split, ldmatrix) ----
        float s[8][4];
#pragma unroll
        for (int nf = 0; nf < 8; nf++)
#pragma unroll
            for (int r = 0; r < 4; r++) s[nf][r] = 0.f;

#pragma unroll
        for (int kf = 0; kf < 8; kf++) {
            const uint32_t qaddr = sb + (w * 16 + a_row) * FROWB + kf * 32 + a_cb;
            uint32_t ah[4], al[4];
            ldsm_x4(ah, qaddr);
            ldsm_x4(al, qaddr + FQ_HALF);
#pragma unroll
            for (int nfp = 0; nfp < 4; nfp++) {
                const uint32_t kaddr = Kst + (nfp * 16 + b_row) * FROWB + kf * 32 + b_cb;
                uint32_t bh4[4], bl4[4];
                ldsm_x4(bh4, kaddr);
                ldsm_x4(bl4, kaddr + FK_HALF);
                mma_bf16(s[2 * nfp],     ah, bh4);
                mma_bf16(s[2 * nfp],     ah, bl4);
                mma_bf16(s[2 * nfp],     al, bh4);
                mma_bf16(s[2 * nfp + 1], ah, bh4 + 2);
                mma_bf16(s[2 * nfp + 1], ah, bl4 + 2);
                mma_bf16(s[2 * nfp + 1], al, bh4 + 2);
            }
        }

        // ---- scale + causal mask + online softmax ----
        const bool diag = (k0 + 63 > q0 + w * 16);
#pragma unroll
        for (int r = 0; r < 2; r++) {
            const int qrow = q0 + w * 16 + lr + 8 * r;
            float mx = -1e30f;
#pragma unroll
            for (int nf = 0; nf < 8; nf++) {
                float v0 = s[nf][2 * r] * scale;
                float v1 = s[nf][2 * r + 1] * scale;
                if (diag) {
                    const int col = k0 + nf * 8 + lc * 2;
                    if (col > qrow) v0 = -1e30f;
                    if (col + 1 > qrow) v1 = -1e30f;
                }
                s[nf][2 * r] = v0;
                s[nf][2 * r + 1] = v1;
                mx = fmaxf(mx, fmaxf(v0, v1));
            }
            mx = fmaxf(mx, __shfl_xor_sync(0xffffffffu, mx, 1));
            mx = fmaxf(mx, __shfl_xor_sync(0xffffffffu, mx, 2));
            const float m_new = fmaxf(mrow[r], mx);
            const float alpha = __expf(mrow[r] - m_new);
            mrow[r] = m_new;
            float sum = 0.f;
#pragma unroll
            for (int nf = 0; nf < 8; nf++) {
                float p0 = __expf(s[nf][2 * r] - m_new);
                float p1 = __expf(s[nf][2 * r + 1] - m_new);
                s[nf][2 * r] = p0;
                s[nf][2 * r + 1] = p1;
                sum += p0 + p1;
            }
            sum += __shfl_xor_sync(0xffffffffu, sum, 1);
            sum += __shfl_xor_sync(0xffffffffu, sum, 2);
            lrow[r] = lrow[r] * alpha + sum;
#pragma unroll
            for (int nf2 = 0; nf2 < 16; nf2++) {
                o[nf2][2 * r] *= alpha;
                o[nf2][2 * r + 1] *= alpha;
            }
        }

        // ---- split P into hi/lo A-fragments (register-only) ----
        uint32_t phi[4][4], plo[4][4];
#pragma unroll
        for (int kf2 = 0; kf2 < 4; kf2++) {
#pragma unroll
            for (int m = 0; m < 2; m++) {
                const int nf = 2 * kf2 + m;
                float x0 = s[nf][0], x1 = s[nf][1], x2 = s[nf][2], x3 = s[nf][3];
                uint32_t h01 = pack2(x0, x1), h23 = pack2(x2, x3);
                phi[kf2][2 * m]     = h01;
                phi[kf2][2 * m + 1] = h23;
                __nv_bfloat162 b01 = *(__nv_bfloat162*)&h01;
                __nv_bfloat162 b23 = *(__nv_bfloat162*)&h23;
                plo[kf2][2 * m]     = pack2(x0 - __bfloat162float(b01.x),
                                            x1 - __bfloat162float(b01.y));
                plo[kf2][2 * m + 1] = pack2(x2 - __bfloat162float(b23.x),
                                            x3 - __bfloat162float(b23.y));
            }
        }

        // ---- O += P V (3-pass split), V fragments via ldmatrix.trans ----
#pragma unroll
        for (int kf2 = 0; kf2 < 4; kf2++) {
#pragma unroll
            for (int nfp = 0; nfp < 8; nfp++) {
                const uint32_t va = Vst + (kf2 * 16 + (lane & 15)) * FROWB
                                    + (nfp * 16 + ((lane >> 4) << 3)) * 2;
                uint32_t bh4[4], bl4[4];
                ldsm_x4_t(bh4, va);
                ldsm_x4_t(bl4, va + FK_HALF);
                mma_bf16(o[2 * nfp],     phi[kf2], bh4);
                mma_bf16(o[2 * nfp],     phi[kf2], bl4);
                mma_bf16(o[2 * nfp],     plo[kf2], bh4);
                mma_bf16(o[2 * nfp + 1], phi[kf2], bh4 + 2);
                mma_bf16(o[2 * nfp + 1], phi[kf2], bl4 + 2);
                mma_bf16(o[2 * nfp + 1], plo[kf2], bh4 + 2);
            }
        }
    }

    // ---- epilogue: write split bf16 hi/lo directly ----
#pragma unroll
    for (int r = 0; r < 2; r++) {
        const float inv = 1.f / lrow[r];
        const int row = q0 + w * 16 + lr + 8 * r;
        const size_t base = ((size_t)(b * Sv + row)) * NQ + h * HDv + lc * 2;
#pragma unroll
        for (int nf2 = 0; nf2 < 16; nf2++) {
            float y0 = o[nf2][2 * r] * inv;
            float y1 = o[nf2][2 * r + 1] * inv;
            uint32_t hw = pack2(y0, y1);
            __nv_bfloat162 hb = *(__nv_bfloat162*)&hw;
            uint32_t lw = pack2(y0 - __bfloat162float(hb.x),
                                y1 - __bfloat162float(hb.y));
            *(uint32_t*)&Oh[base + nf2 * 8] = hw;
            *(uint32_t*)&Ol[base + nf2 * 8] = lw;
        }
    }
}

// ---------------------------------------------------------------------------
// Launch. Inputs: 0=x 1=cos 2=sin 3=positions 4=mask 5=wq 6=wk 7=wv 8=wo
// ---------------------------------------------------------------------------
extern "C" void kernel_launch(void* const* d_in, const int* in_sizes, int n_in,
                              void* d_out, int out_size)
{
    const float* x  = (const float*)d_in[0];
    const float* fc = (const float*)d_in[1];
    const float* fs = (const float*)d_in[2];
    const float* wq = (const float*)d_in[5];
    const float* wk = (const float*)d_in[6];
    const float* wv = (const float*)d_in[7];
    const float* wo = (const float*)d_in[8];
    float* out = (float*)d_out;

    float *q, *k, *v;
    cudaGetSymbolAddress((void**)&q, g_q);
    cudaGetSymbolAddress((void**)&k, g_k);
    cudaGetSymbolAddress((void**)&v, g_v);
    __nv_bfloat16 *xh, *xl, *qh, *ql, *kh, *kl, *vh, *vl, *oh, *ol, *ah, *al;
    __nv_bfloat16 *qrh, *qrl, *krh, *krl, *vsh, *vsl;
    cudaGetSymbolAddress((void**)&xh, g_x_hi);  cudaGetSymbolAddress((void**)&xl, g_x_lo);
    cudaGetSymbolAddress((void**)&qh, g_wq_hi); cudaGetSymbolAddress((void**)&ql, g_wq_lo);
    cudaGetSymbolAddress((void**)&kh, g_wk_hi); cudaGetSymbolAddress((void**)&kl, g_wk_lo);
    cudaGetSymbolAddress((void**)&vh, g_wv_hi); cudaGetSymbolAddress((void**)&vl, g_wv_lo);
    cudaGetSymbolAddress((void**)&oh, g_wo_hi); cudaGetSymbolAddress((void**)&ol, g_wo_lo);
    cudaGetSymbolAddress((void**)&ah, g_at_hi); cudaGetSymbolAddress((void**)&al, g_at_lo);
    cudaGetSymbolAddress((void**)&qrh, g_qr_hi); cudaGetSymbolAddress((void**)&qrl, g_qr_lo);
    cudaGetSymbolAddress((void**)&krh, g_kr_hi); cudaGetSymbolAddress((void**)&krl, g_kr_lo);
    cudaGetSymbolAddress((void**)&vsh, g_vs_hi); cudaGetSymbolAddress((void**)&vsl, g_vs_lo);

    // split conversions for projections
    {
        long n4;
        n4 = (long)Mv * Dv / 4;  cvt_split<<<(unsigned)((n4 + 255) / 256), 256>>>(x,  xh, xl, n4);
        n4 = (long)NQ * Dv / 4;  cvt_split<<<(unsigned)((n4 + 255) / 256), 256>>>(wq, qh, ql, n4);
        n4 = (long)NKV * Dv / 4; cvt_split<<<(unsigned)((n4 + 255) / 256), 256>>>(wk, kh, kl, n4);
        n4 = (long)NKV * Dv / 4; cvt_split<<<(unsigned)((n4 + 255) / 256), 256>>>(wv, vh, vl, n4);
        n4 = (long)Dv * NQ / 4;  cvt_split<<<(unsigned)((n4 + 255) / 256), 256>>>(wo, oh, ol, n4);
    }

    cudaFuncSetAttribute(gemm_hmma_x3, cudaFuncAttributeMaxDynamicSharedMemorySize, GEMM_SMEM);

    // QKV projections
    gemm_hmma_x3<<<dim3(NQ / BN,  Mv / BM), 256, GEMM_SMEM>>>(xh, xl, qh, ql, q, NQ,  Dv);
    gemm_hmma_x3<<<dim3(NKV / BN, Mv / BM), 256, GEMM_SMEM>>>(xh, xl, kh, kl, k, NKV, Dv);
    gemm_hmma_x3<<<dim3(NKV / BN, Mv / BM), 256, GEMM_SMEM>>>(xh, xl, vh, vl, v, NKV, Dv);

    // RoPE + split for Q,K; split for V
    {
        long nq_pairs = (long)Mv * Hv * (HDv / 2);
        long nk_pairs = (long)Mv * KVHv * (HDv / 2);
        rope_split<<<(unsigned)((nq_pairs + 255) / 256), 256>>>(q, qrh, qrl, fc, fs, Hv);
        rope_split<<<(unsigned)((nk_pairs + 255) / 256), 256>>>(k, krh, krl, fc, fs, KVHv);
        long n4 = (long)Mv * NKV / 4;
        cvt_split<<<(unsigned)((n4 + 255) / 256), 256>>>(v, vsh, vsl, n4);
    }

    // HMMA flash attention (writes split bf16 directly)
    cudaFuncSetAttribute(flash_hmma, cudaFuncAttributeMaxDynamicSharedMemorySize, FLASH_SMEM);
    flash_hmma<<<dim3(Sv / 128, Hv, Bv), 256, FLASH_SMEM>>>(
        qrh, qrl, krh, krl, vsh, vsl, ah, al);

    // Output projection
    gemm_hmma_x3<<<dim3(NQ / BN, Mv / BM), 256, GEMM_SMEM>>>(ah, al, oh, ol, out, NQ, Dv);
}

// round 6
// speedup vs baseline: 3.6461x; 1.1563x over previous
#include <cuda_runtime.h>
#include <cuda_bf16.h>
#include <cstdint>
#include <math.h>

// Problem constants
#define Bv   2
#define Sv   2048
#define Dv   4096
#define Hv   32
#define KVHv 8
#define HDv  128
#define Mv   (Bv * Sv)       // 4096
#define NQ   (Hv * HDv)      // 4096
#define NKV  (KVHv * HDv)    // 1024
#define NQKV (NQ + 2 * NKV)  // 6144

// bf16 split-precision scratch
__device__ __nv_bfloat16 g_x_hi[(size_t)Mv * Dv],    g_x_lo[(size_t)Mv * Dv];
__device__ __nv_bfloat16 g_wqkv_hi[(size_t)NQKV * Dv], g_wqkv_lo[(size_t)NQKV * Dv];
__device__ __nv_bfloat16 g_wo_hi[(size_t)Dv * NQ],   g_wo_lo[(size_t)Dv * NQ];
__device__ __nv_bfloat16 g_at_hi[(size_t)Mv * NQ],   g_at_lo[(size_t)Mv * NQ];
// rope'd / split Q,K,V for flash
__device__ __nv_bfloat16 g_qr_hi[(size_t)Mv * NQ],  g_qr_lo[(size_t)Mv * NQ];
__device__ __nv_bfloat16 g_kr_hi[(size_t)Mv * NKV], g_kr_lo[(size_t)Mv * NKV];
__device__ __nv_bfloat16 g_vs_hi[(size_t)Mv * NKV], g_vs_lo[(size_t)Mv * NKV];

// ---------------------------------------------------------------------------
// Helpers (compute_103-safe)
// ---------------------------------------------------------------------------
__device__ __forceinline__ uint32_t smem_u32(const void* p) {
    uint32_t a;
    asm("{ .reg .u64 t; cvta.to.shared.u64 t, %1; cvt.u32.u64 %0, t; }" : "=r"(a) : "l"(p));
    return a;
}
__device__ __forceinline__ void cp16(uint32_t dst, const void* src) {
    asm volatile("cp.async.cg.shared.global [%0], [%1], 16;" :: "r"(dst), "l"(src));
}
#define CP_COMMIT() asm volatile("cp.async.commit_group;" ::: "memory")
#define CP_WAIT0()  asm volatile("cp.async.wait_group 0;" ::: "memory")

__device__ __forceinline__ void mma_bf16(float* c, const uint32_t* a, const uint32_t* b) {
    asm volatile("mma.sync.aligned.m16n8k16.row.col.f32.bf16.bf16.f32 "
        "{%0,%1,%2,%3}, {%4,%5,%6,%7}, {%8,%9}, {%0,%1,%2,%3};"
        : "+f"(c[0]), "+f"(c[1]), "+f"(c[2]), "+f"(c[3])
        : "r"(a[0]), "r"(a[1]), "r"(a[2]), "r"(a[3]), "r"(b[0]), "r"(b[1]));
}
__device__ __forceinline__ void ldsm_x4(uint32_t* r, uint32_t addr) {
    asm volatile("ldmatrix.sync.aligned.m8n8.x4.shared.b16 {%0,%1,%2,%3}, [%4];"
        : "=r"(r[0]), "=r"(r[1]), "=r"(r[2]), "=r"(r[3]) : "r"(addr));
}
__device__ __forceinline__ void ldsm_x4_t(uint32_t* r, uint32_t addr) {
    asm volatile("ldmatrix.sync.aligned.m8n8.x4.trans.shared.b16 {%0,%1,%2,%3}, [%4];"
        : "=r"(r[0]), "=r"(r[1]), "=r"(r[2]), "=r"(r[3]) : "r"(addr));
}
__device__ __forceinline__ uint32_t pack2(float x, float y) {
    __nv_bfloat162 t = __floats2bfloat162_rn(x, y);
    return *(uint32_t*)&t;
}

// ---------------------------------------------------------------------------
// Split fp32 -> bf16 hi/lo
// ---------------------------------------------------------------------------
__global__ void cvt_split(const float* __restrict__ in,
                          __nv_bfloat16* __restrict__ hi,
                          __nv_bfloat16* __restrict__ lo, long n4) {
    long i = (long)blockIdx.x * blockDim.x + threadIdx.x;
    if (i >= n4) return;
    float4 v = ((const float4*)in)[i];
    __nv_bfloat16 h[4], l[4];
    float vv[4] = {v.x, v.y, v.z, v.w};
#pragma unroll
    for (int j = 0; j < 4; j++) {
        h[j] = __float2bfloat16(vv[j]);
        l[j] = __float2bfloat16(vv[j] - __bfloat162float(h[j]));
    }
    ((__nv_bfloat162*)hi)[i * 2]     = __nv_bfloat162(h[0], h[1]);
    ((__nv_bfloat162*)hi)[i * 2 + 1] = __nv_bfloat162(h[2], h[3]);
    ((__nv_bfloat162*)lo)[i * 2]     = __nv_bfloat162(l[0], l[1]);
    ((__nv_bfloat162*)lo)[i * 2 + 1] = __nv_bfloat162(l[2], l[3]);
}

// ---------------------------------------------------------------------------
// HMMA bf16x3 GEMM, 2-stage pipeline, 80KB smem, 2 CTAs/SM.
// 128x128 CTA tile, BK=32, 8 warps (64x32 each), ldmatrix fragment loads.
// EPI=1: fused RoPE + hi/lo-split epilogue (QKV); EPI=0: fp32 C.
// ---------------------------------------------------------------------------
#define BM 128
#define BN 128
#define BK 32
#define ROW_STRIDE 80
#define TILE_SM   (128 * ROW_STRIDE)
#define STAGE_SM  (4 * TILE_SM)       // Ahi, Alo, Bhi, Blo = 40960 B
#define GEMM_SMEM (2 * STAGE_SM)      // 81920 B

__device__ __forceinline__ void load_stage(
    uint32_t sbase,
    const __nv_bfloat16* __restrict__ Ahi, const __nv_bfloat16* __restrict__ Alo,
    const __nv_bfloat16* __restrict__ Bhi, const __nv_bfloat16* __restrict__ Blo,
    int m0, int n0, int k0, int K, int tid)
{
#pragma unroll
    for (int j = 0; j < 8; j++) {
        const int tile = j >> 1;
        const int cc = tid + (j & 1) * 256;
        const int row = cc >> 2;
        const int c16 = cc & 3;
        const uint32_t soff = sbase + tile * TILE_SM + row * ROW_STRIDE + c16 * 16;
        const __nv_bfloat16* g =
            (tile == 0) ? Ahi : (tile == 1) ? Alo : (tile == 2) ? Bhi : Blo;
        const int grow = (tile < 2) ? (m0 + row) : (n0 + row);
        cp16(soff, g + (size_t)grow * K + k0 + c16 * 8);
    }
}

template <bool EPI>
__global__ __launch_bounds__(256, 2) void gemm_hmma_x3(
    const __nv_bfloat16* __restrict__ Ahi, const __nv_bfloat16* __restrict__ Alo,
    const __nv_bfloat16* __restrict__ Bhi, const __nv_bfloat16* __restrict__ Blo,
    float* __restrict__ C,
    __nv_bfloat16* __restrict__ Qh, __nv_bfloat16* __restrict__ Ql,
    __nv_bfloat16* __restrict__ Kh, __nv_bfloat16* __restrict__ Kl,
    __nv_bfloat16* __restrict__ Vh, __nv_bfloat16* __restrict__ Vl,
    const float* __restrict__ cs, const float* __restrict__ sn,
    int N, int K)
{
    extern __shared__ char smem[];
    const uint32_t sb = smem_u32(smem);
    const int tid = threadIdx.x;
    const int wid = tid >> 5, lane = tid & 31;
    const int wm = wid & 1;
    const int wn = wid >> 1;
    const int lr = lane >> 2;
    const int m0 = blockIdx.y * BM, n0 = blockIdx.x * BN;

    float acc[4][4][4];
#pragma unroll
    for (int mt = 0; mt < 4; mt++)
#pragma unroll
        for (int nt = 0; nt < 4; nt++)
#pragma unroll
            for (int r = 0; r < 4; r++) acc[mt][nt][r] = 0.f;

    const int NIT = K / BK;

    load_stage(sb, Ahi, Alo, Bhi, Blo, m0, n0, 0, K, tid);
    CP_COMMIT();

    const int a_row = lane & 15;
    const int a_cb  = (lane >> 4) << 4;
    const int b_row = (lane & 7) + ((lane >> 4) << 3);
    const int b_cb  = ((lane >> 3) & 1) << 4;

    for (int it = 0; it < NIT; ++it) {
        CP_WAIT0();            // stage it&1 resident
        __syncthreads();       // all warps done with compute(it-1) -> other buf free
        if (it + 1 < NIT) {
            load_stage(sb + ((it + 1) & 1) * STAGE_SM,
                       Ahi, Alo, Bhi, Blo, m0, n0, (it + 1) * BK, K, tid);
            CP_COMMIT();
        }

        const uint32_t sA = sb + (it & 1) * STAGE_SM;
        const uint32_t sB = sA + 2 * TILE_SM;
#pragma unroll
        for (int kk = 0; kk < 2; kk++) {
            uint32_t ah[4][4], al[4][4], bh[2][4], bl[2][4];
#pragma unroll
            for (int mt = 0; mt < 4; mt++) {
                const uint32_t aaddr = sA + (wm * 64 + mt * 16 + a_row) * ROW_STRIDE
                                       + kk * 32 + a_cb;
                ldsm_x4(ah[mt], aaddr);
                ldsm_x4(al[mt], aaddr + TILE_SM);
            }
#pragma unroll
            for (int ntp = 0; ntp < 2; ntp++) {
                const uint32_t baddr = sB + (wn * 32 + ntp * 16 + b_row) * ROW_STRIDE
                                       + kk * 32 + b_cb;
                ldsm_x4(bh[ntp], baddr);
                ldsm_x4(bl[ntp], baddr + TILE_SM);
            }
#pragma unroll
            for (int mt = 0; mt < 4; mt++)
#pragma unroll
                for (int nt = 0; nt < 4; nt++) {
                    const uint32_t* bhf = bh[nt >> 1] + (nt & 1) * 2;
                    const uint32_t* blf = bl[nt >> 1] + (nt & 1) * 2;
                    mma_bf16(acc[mt][nt], ah[mt], bhf);
                    mma_bf16(acc[mt][nt], ah[mt], blf);
                    mma_bf16(acc[mt][nt], al[mt], bhf);
                }
        }
    }

    if (!EPI) {
        // fp32 epilogue
#pragma unroll
        for (int mt = 0; mt < 4; mt++) {
            const int row = m0 + wm * 64 + mt * 16 + lr;
#pragma unroll
            for (int nt = 0; nt < 4; nt++) {
                const int col = n0 + wn * 32 + nt * 8 + (lane & 3) * 2;
                float2* p0 = (float2*)&C[(size_t)row * N + col];
                float2* p1 = (float2*)&C[(size_t)(row + 8) * N + col];
                *p0 = make_float2(acc[mt][nt][0], acc[mt][nt][1]);
                *p1 = make_float2(acc[mt][nt][2], acc[mt][nt][3]);
            }
        }
    } else {
        // fused RoPE + hi/lo split epilogue; region uniform per CTA
        __nv_bfloat16 *Dh, *Dl;
        int dstride, coff;
        bool dorope;
        if (n0 < NQ)             { Dh = Qh; Dl = Ql; dstride = NQ;  coff = 0;         dorope = true; }
        else if (n0 < NQ + NKV)  { Dh = Kh; Dl = Kl; dstride = NKV; coff = NQ;        dorope = true; }
        else                     { Dh = Vh; Dl = Vl; dstride = NKV; coff = NQ + NKV;  dorope = false; }
#pragma unroll
        for (int mt = 0; mt < 4; mt++) {
#pragma unroll
            for (int nt = 0; nt < 4; nt++) {
                const int col = n0 + wn * 32 + nt * 8 + (lane & 3) * 2;
                const int fi = (col & 127) >> 1;   // rope freq index
#pragma unroll
                for (int r = 0; r < 2; r++) {
                    const int row = m0 + wm * 64 + mt * 16 + lr + 8 * r;
                    float x0 = acc[mt][nt][2 * r];
                    float x1 = acc[mt][nt][2 * r + 1];
                    float y0 = x0, y1 = x1;
                    if (dorope) {
                        const int s = row & (Sv - 1);
                        const float c  = __ldg(cs + s * 64 + fi);
                        const float sv = __ldg(sn + s * 64 + fi);
                        y0 = x0 * c - x1 * sv;
                        y1 = x0 * sv + x1 * c;
                    }
                    uint32_t hw = pack2(y0, y1);
                    __nv_bfloat162 hb = *(__nv_bfloat162*)&hw;
                    uint32_t lw = pack2(y0 - __bfloat162float(hb.x),
                                        y1 - __bfloat162float(hb.y));
                    const size_t o = (size_t)row * dstride + (col - coff);
                    *(uint32_t*)&Dh[o] = hw;
                    *(uint32_t*)&Dl[o] = lw;
                }
            }
        }
    }
}

// ---------------------------------------------------------------------------
// HMMA flash attention (split-bf16 x3, ldmatrix). Unchanged from R5.
// ---------------------------------------------------------------------------
#define FROWB 272
#define FQ_HALF (128 * FROWB)
#define FK_HALF (64 * FROWB)
#define SM_K0   (2 * FQ_HALF)
#define SM_V0   (SM_K0 + 4 * FK_HALF)
#define FLASH_SMEM (SM_V0 + 4 * FK_HALF)

__device__ __forceinline__ void flash_load_kv(
    uint32_t sb, int stage,
    const __nv_bfloat16* __restrict__ Kh, const __nv_bfloat16* __restrict__ Kl,
    const __nv_bfloat16* __restrict__ Vh, const __nv_bfloat16* __restrict__ Vl,
    size_t gbase, int tid)
{
#pragma unroll
    for (int j = 0; j < 16; j++) {
        const int t = j >> 2;
        const int cc = tid + (j & 3) * 256;
        const int row = cc >> 4, c16 = cc & 15;
        const __nv_bfloat16* g = (t == 0) ? Kh : (t == 1) ? Kl : (t == 2) ? Vh : Vl;
        const uint32_t soff = sb + ((t < 2) ? SM_K0 : SM_V0) + stage * 2 * FK_HALF
                              + (t & 1) * FK_HALF + row * FROWB + c16 * 16;
        cp16(soff, g + gbase + (size_t)row * NKV + c16 * 8);
    }
}

__global__ __launch_bounds__(256, 1) void flash_hmma(
    const __nv_bfloat16* __restrict__ Qh_g, const __nv_bfloat16* __restrict__ Ql_g,
    const __nv_bfloat16* __restrict__ Kh_g, const __nv_bfloat16* __restrict__ Kl_g,
    const __nv_bfloat16* __restrict__ Vh_g, const __nv_bfloat16* __restrict__ Vl_g,
    __nv_bfloat16* __restrict__ Oh, __nv_bfloat16* __restrict__ Ol)
{
    extern __shared__ char smem[];
    const uint32_t sb = smem_u32(smem);
    const int tid = threadIdx.x, w = tid >> 5, lane = tid & 31;
    const int lr = lane >> 2, lc = lane & 3;
    const int q0 = blockIdx.x * 128, h = blockIdx.y, b = blockIdx.z;
    const int kvh = h >> 2;
    const float scale = 0.08838834764831845f;

    {
        const size_t gq = ((size_t)(b * Sv + q0)) * NQ + h * HDv;
#pragma unroll
        for (int j = 0; j < 16; j++) {
            const int hl = j >> 3;
            const int cc = tid + (j & 7) * 256;
            const int row = cc >> 4, c16 = cc & 15;
            const __nv_bfloat16* g = hl ? Ql_g : Qh_g;
            cp16(sb + hl * FQ_HALF + row * FROWB + c16 * 16,
                 g + gq + (size_t)row * NQ + c16 * 8);
        }
    }
    const int ktmax = 2 * blockIdx.x + 1;
    flash_load_kv(sb, 0, Kh_g, Kl_g, Vh_g, Vl_g,
                  ((size_t)(b * Sv)) * NKV + kvh * HDv, tid);
    CP_COMMIT();

    float o[16][4];
#pragma unroll
    for (int i = 0; i < 16; i++)
#pragma unroll
        for (int j = 0; j < 4; j++) o[i][j] = 0.f;
    float mrow[2] = {-1e30f, -1e30f};
    float lrow[2] = {0.f, 0.f};

    const int a_row = lane & 15;
    const int a_cb  = (lane >> 4) << 4;
    const int b_row = (lane & 7) + ((lane >> 4) << 3);
    const int b_cb  = ((lane >> 3) & 1) << 4;

    for (int kt = 0; kt <= ktmax; ++kt) {
        CP_WAIT0();
        __syncthreads();
        if (kt < ktmax) {
            flash_load_kv(sb, (kt + 1) & 1, Kh_g, Kl_g, Vh_g, Vl_g,
                          ((size_t)(b * Sv + (kt + 1) * 64)) * NKV + kvh * HDv, tid);
            CP_COMMIT();
        }

        const int k0 = kt * 64;
        if (k0 > q0 + w * 16 + 15) continue;

        const uint32_t Kst = sb + SM_K0 + (kt & 1) * 2 * FK_HALF;
        const uint32_t Vst = sb + SM_V0 + (kt & 1) * 2 * FK_HALF;

        float s[8][4];
#pragma unroll
        for (int nf = 0; nf < 8; nf++)
#pragma unroll
            for (int r = 0; r < 4; r++) s[nf][r] = 0.f;

#pragma unroll
        for (int kf = 0; kf < 8; kf++) {
            const uint32_t qaddr = sb + (w * 16 + a_row) * FROWB + kf * 32 + a_cb;
            uint32_t ah[4], al[4];
            ldsm_x4(ah, qaddr);
            ldsm_x4(al, qaddr + FQ_HALF);
#pragma unroll
            for (int nfp = 0; nfp < 4; nfp++) {
                const uint32_t kaddr = Kst + (nfp * 16 + b_row) * FROWB + kf * 32 + b_cb;
                uint32_t bh4[4], bl4[4];
                ldsm_x4(bh4, kaddr);
                ldsm_x4(bl4, kaddr + FK_HALF);
                mma_bf16(s[2 * nfp],     ah, bh4);
                mma_bf16(s[2 * nfp],     ah, bl4);
                mma_bf16(s[2 * nfp],     al, bh4);
                mma_bf16(s[2 * nfp + 1], ah, bh4 + 2);
                mma_bf16(s[2 * nfp + 1], ah, bl4 + 2);
                mma_bf16(s[2 * nfp + 1], al, bh4 + 2);
            }
        }

        const bool diag = (k0 + 63 > q0 + w * 16);
#pragma unroll
        for (int r = 0; r < 2; r++) {
            const int qrow = q0 + w * 16 + lr + 8 * r;
            float mx = -1e30f;
#pragma unroll
            for (int nf = 0; nf < 8; nf++) {
                float v0 = s[nf][2 * r] * scale;
                float v1 = s[nf][2 * r + 1] * scale;
                if (diag) {
                    const int col = k0 + nf * 8 + lc * 2;
                    if (col > qrow) v0 = -1e30f;
                    if (col + 1 > qrow) v1 = -1e30f;
                }
                s[nf][2 * r] = v0;
                s[nf][2 * r + 1] = v1;
                mx = fmaxf(mx, fmaxf(v0, v1));
            }
            mx = fmaxf(mx, __shfl_xor_sync(0xffffffffu, mx, 1));
            mx = fmaxf(mx, __shfl_xor_sync(0xffffffffu, mx, 2));
            const float m_new = fmaxf(mrow[r], mx);
            const float alpha = __expf(mrow[r] - m_new);
            mrow[r] = m_new;
            float sum = 0.f;
#pragma unroll
            for (int nf = 0; nf < 8; nf++) {
                float p0 = __expf(s[nf][2 * r] - m_new);
                float p1 = __expf(s[nf][2 * r + 1] - m_new);
                s[nf][2 * r] = p0;
                s[nf][2 * r + 1] = p1;
                sum += p0 + p1;
            }
            sum += __shfl_xor_sync(0xffffffffu, sum, 1);
            sum += __shfl_xor_sync(0xffffffffu, sum, 2);
            lrow[r] = lrow[r] * alpha + sum;
#pragma unroll
            for (int nf2 = 0; nf2 < 16; nf2++) {
                o[nf2][2 * r] *= alpha;
                o[nf2][2 * r + 1] *= alpha;
            }
        }

        uint32_t phi[4][4], plo[4][4];
#pragma unroll
        for (int kf2 = 0; kf2 < 4; kf2++) {
#pragma unroll
            for (int m = 0; m < 2; m++) {
                const int nf = 2 * kf2 + m;
                float x0 = s[nf][0], x1 = s[nf][1], x2 = s[nf][2], x3 = s[nf][3];
                uint32_t h01 = pack2(x0, x1), h23 = pack2(x2, x3);
                phi[kf2][2 * m]     = h01;
                phi[kf2][2 * m + 1] = h23;
                __nv_bfloat162 b01 = *(__nv_bfloat162*)&h01;
                __nv_bfloat162 b23 = *(__nv_bfloat162*)&h23;
                plo[kf2][2 * m]     = pack2(x0 - __bfloat162float(b01.x),
                                            x1 - __bfloat162float(b01.y));
                plo[kf2][2 * m + 1] = pack2(x2 - __bfloat162float(b23.x),
                                            x3 - __bfloat162float(b23.y));
            }
        }

#pragma unroll
        for (int kf2 = 0; kf2 < 4; kf2++) {
#pragma unroll
            for (int nfp = 0; nfp < 8; nfp++) {
                const uint32_t va = Vst + (kf2 * 16 + (lane & 15)) * FROWB
                                    + (nfp * 16 + ((lane >> 4) << 3)) * 2;
                uint32_t bh4[4], bl4[4];
                ldsm_x4_t(bh4, va);
                ldsm_x4_t(bl4, va + FK_HALF);
                mma_bf16(o[2 * nfp],     phi[kf2], bh4);
                mma_bf16(o[2 * nfp],     phi[kf2], bl4);
                mma_bf16(o[2 * nfp],     plo[kf2], bh4);
                mma_bf16(o[2 * nfp + 1], phi[kf2], bh4 + 2);
                mma_bf16(o[2 * nfp + 1], phi[kf2], bl4 + 2);
                mma_bf16(o[2 * nfp + 1], plo[kf2], bh4 + 2);
            }
        }
    }

#pragma unroll
    for (int r = 0; r < 2; r++) {
        const float inv = 1.f / lrow[r];
        const int row = q0 + w * 16 + lr + 8 * r;
        const size_t base = ((size_t)(b * Sv + row)) * NQ + h * HDv + lc * 2;
#pragma unroll
        for (int nf2 = 0; nf2 < 16; nf2++) {
            float y0 = o[nf2][2 * r] * inv;
            float y1 = o[nf2][2 * r + 1] * inv;
            uint32_t hw = pack2(y0, y1);
            __nv_bfloat162 hb = *(__nv_bfloat162*)&hw;
            uint32_t lw = pack2(y0 - __bfloat162float(hb.x),
                                y1 - __bfloat162float(hb.y));
            *(uint32_t*)&Oh[base + nf2 * 8] = hw;
            *(uint32_t*)&Ol[base + nf2 * 8] = lw;
        }
    }
}

// ---------------------------------------------------------------------------
// Launch. Inputs: 0=x 1=cos 2=sin 3=positions 4=mask 5=wq 6=wk 7=wv 8=wo
// ---------------------------------------------------------------------------
extern "C" void kernel_launch(void* const* d_in, const int* in_sizes, int n_in,
                              void* d_out, int out_size)
{
    const float* x  = (const float*)d_in[0];
    const float* fc = (const float*)d_in[1];
    const float* fs = (const float*)d_in[2];
    const float* wq = (const float*)d_in[5];
    const float* wk = (const float*)d_in[6];
    const float* wv = (const float*)d_in[7];
    const float* wo = (const float*)d_in[8];
    float* out = (float*)d_out;

    __nv_bfloat16 *xh, *xl, *wh, *wl, *oh, *ol, *ah, *al;
    __nv_bfloat16 *qrh, *qrl, *krh, *krl, *vsh, *vsl;
    cudaGetSymbolAddress((void**)&xh, g_x_hi);    cudaGetSymbolAddress((void**)&xl, g_x_lo);
    cudaGetSymbolAddress((void**)&wh, g_wqkv_hi); cudaGetSymbolAddress((void**)&wl, g_wqkv_lo);
    cudaGetSymbolAddress((void**)&oh, g_wo_hi);   cudaGetSymbolAddress((void**)&ol, g_wo_lo);
    cudaGetSymbolAddress((void**)&ah, g_at_hi);   cudaGetSymbolAddress((void**)&al, g_at_lo);
    cudaGetSymbolAddress((void**)&qrh, g_qr_hi);  cudaGetSymbolAddress((void**)&qrl, g_qr_lo);
    cudaGetSymbolAddress((void**)&krh, g_kr_hi);  cudaGetSymbolAddress((void**)&krl, g_kr_lo);
    cudaGetSymbolAddress((void**)&vsh, g_vs_hi);  cudaGetSymbolAddress((void**)&vsl, g_vs_lo);

    // split conversions (weights concatenated into g_wqkv)
    {
        long n4;
        n4 = (long)Mv * Dv / 4;
        cvt_split<<<(unsigned)((n4 + 255) / 256), 256>>>(x, xh, xl, n4);
        n4 = (long)NQ * Dv / 4;
        cvt_split<<<(unsigned)((n4 + 255) / 256), 256>>>(wq, wh, wl, n4);
        n4 = (long)NKV * Dv / 4;
        cvt_split<<<(unsigned)((n4 + 255) / 256), 256>>>(
            wk, wh + (size_t)NQ * Dv, wl + (size_t)NQ * Dv, n4);
        cvt_split<<<(unsigned)((n4 + 255) / 256), 256>>>(
            wv, wh + (size_t)(NQ + NKV) * Dv, wl + (size_t)(NQ + NKV) * Dv, n4);
        n4 = (long)Dv * NQ / 4;
        cvt_split<<<(unsigned)((n4 + 255) / 256), 256>>>(wo, oh, ol, n4);
    }

    cudaFuncSetAttribute(gemm_hmma_x3<true>,
                         cudaFuncAttributeMaxDynamicSharedMemorySize, GEMM_SMEM);
    cudaFuncSetAttribute(gemm_hmma_x3<false>,
                         cudaFuncAttributeMaxDynamicSharedMemorySize, GEMM_SMEM);

    // Fused QKV projection + RoPE + split
    gemm_hmma_x3<true><<<dim3(NQKV / BN, Mv / BM), 256, GEMM_SMEM>>>(
        xh, xl, wh, wl, nullptr,
        qrh, qrl, krh, krl, vsh, vsl, fc, fs, NQKV, Dv);

    // HMMA flash attention (writes split bf16 directly)
    cudaFuncSetAttribute(flash_hmma, cudaFuncAttributeMaxDynamicSharedMemorySize, FLASH_SMEM);
    flash_hmma<<<dim3(Sv / 128, Hv, Bv), 256, FLASH_SMEM>>>(
        qrh, qrl, krh, krl, vsh, vsl, ah, al);

    // Output projection
    gemm_hmma_x3<false><<<dim3(NQ / BN, Mv / BM), 256, GEMM_SMEM>>>(
        ah, al, oh, ol, out,
        nullptr, nullptr, nullptr, nullptr, nullptr, nullptr, nullptr, nullptr,
        NQ, Dv);
}

// round 7
// speedup vs baseline: 3.9655x; 1.0876x over previous
#include <cuda_runtime.h>
#include <cuda_bf16.h>
#include <cstdint>
#include <math.h>

// Problem constants
#define Bv   2
#define Sv   2048
#define Dv   4096
#define Hv   32
#define KVHv 8
#define HDv  128
#define Mv   (Bv * Sv)       // 4096
#define NQ   (Hv * HDv)      // 4096
#define NKV  (KVHv * HDv)    // 1024
#define NQKV (NQ + 2 * NKV)  // 6144

// bf16 split-precision scratch
__device__ __nv_bfloat16 g_x_hi[(size_t)Mv * Dv],    g_x_lo[(size_t)Mv * Dv];
__device__ __nv_bfloat16 g_wqkv_hi[(size_t)NQKV * Dv], g_wqkv_lo[(size_t)NQKV * Dv];
__device__ __nv_bfloat16 g_wo_hi[(size_t)Dv * NQ],   g_wo_lo[(size_t)Dv * NQ];
__device__ __nv_bfloat16 g_at_hi[(size_t)Mv * NQ],   g_at_lo[(size_t)Mv * NQ];
// rope'd / split Q,K,V for flash
__device__ __nv_bfloat16 g_qr_hi[(size_t)Mv * NQ],  g_qr_lo[(size_t)Mv * NQ];
__device__ __nv_bfloat16 g_kr_hi[(size_t)Mv * NKV], g_kr_lo[(size_t)Mv * NKV];
__device__ __nv_bfloat16 g_vs_hi[(size_t)Mv * NKV], g_vs_lo[(size_t)Mv * NKV];

// ---------------------------------------------------------------------------
// Helpers (compute_103-safe)
// ---------------------------------------------------------------------------
__device__ __forceinline__ uint32_t smem_u32(const void* p) {
    uint32_t a;
    asm("{ .reg .u64 t; cvta.to.shared.u64 t, %1; cvt.u32.u64 %0, t; }" : "=r"(a) : "l"(p));
    return a;
}
__device__ __forceinline__ void cp16(uint32_t dst, const void* src) {
    asm volatile("cp.async.cg.shared.global [%0], [%1], 16;" :: "r"(dst), "l"(src));
}
#define CP_COMMIT() asm volatile("cp.async.commit_group;" ::: "memory")
#define CP_WAIT1()  asm volatile("cp.async.wait_group 1;" ::: "memory")
#define CP_WAIT0()  asm volatile("cp.async.wait_group 0;" ::: "memory")

__device__ __forceinline__ void mma_bf16(float* c, const uint32_t* a, const uint32_t* b) {
    asm volatile("mma.sync.aligned.m16n8k16.row.col.f32.bf16.bf16.f32 "
        "{%0,%1,%2,%3}, {%4,%5,%6,%7}, {%8,%9}, {%0,%1,%2,%3};"
        : "+f"(c[0]), "+f"(c[1]), "+f"(c[2]), "+f"(c[3])
        : "r"(a[0]), "r"(a[1]), "r"(a[2]), "r"(a[3]), "r"(b[0]), "r"(b[1]));
}
__device__ __forceinline__ void ldsm_x4(uint32_t* r, uint32_t addr) {
    asm volatile("ldmatrix.sync.aligned.m8n8.x4.shared.b16 {%0,%1,%2,%3}, [%4];"
        : "=r"(r[0]), "=r"(r[1]), "=r"(r[2]), "=r"(r[3]) : "r"(addr));
}
__device__ __forceinline__ void ldsm_x4_t(uint32_t* r, uint32_t addr) {
    asm volatile("ldmatrix.sync.aligned.m8n8.x4.trans.shared.b16 {%0,%1,%2,%3}, [%4];"
        : "=r"(r[0]), "=r"(r[1]), "=r"(r[2]), "=r"(r[3]) : "r"(addr));
}
__device__ __forceinline__ uint32_t pack2(float x, float y) {
    __nv_bfloat162 t = __floats2bfloat162_rn(x, y);
    return *(uint32_t*)&t;
}

// ---------------------------------------------------------------------------
// Split fp32 -> bf16 hi/lo
// ---------------------------------------------------------------------------
__global__ void cvt_split(const float* __restrict__ in,
                          __nv_bfloat16* __restrict__ hi,
                          __nv_bfloat16* __restrict__ lo, long n4) {
    long i = (long)blockIdx.x * blockDim.x + threadIdx.x;
    if (i >= n4) return;
    float4 v = ((const float4*)in)[i];
    __nv_bfloat16 h[4], l[4];
    float vv[4] = {v.x, v.y, v.z, v.w};
#pragma unroll
    for (int j = 0; j < 4; j++) {
        h[j] = __float2bfloat16(vv[j]);
        l[j] = __float2bfloat16(vv[j] - __bfloat162float(h[j]));
    }
    ((__nv_bfloat162*)hi)[i * 2]     = __nv_bfloat162(h[0], h[1]);
    ((__nv_bfloat162*)hi)[i * 2 + 1] = __nv_bfloat162(h[2], h[3]);
    ((__nv_bfloat162*)lo)[i * 2]     = __nv_bfloat162(l[0], l[1]);
    ((__nv_bfloat162*)lo)[i * 2 + 1] = __nv_bfloat162(l[2], l[3]);
}

// ---------------------------------------------------------------------------
// HMMA bf16x3 GEMM, 3-stage pipeline, 96KB smem, 2 CTAs/SM.
// 128x128 CTA tile, BK=32, 8 warps (64x32 each), ldmatrix fragment loads.
// Swizzled 64B smem rows: c16' = c16 ^ ((row>>1)&3) -> all ldmatrix phases
// and cp.async stores hit distinct bank quads.
// EPI=1: fused RoPE + hi/lo-split epilogue (QKV); EPI=0: fp32 C.
// ---------------------------------------------------------------------------
#define BM 128
#define BN 128
#define BK 32
#define TILE_SM   (128 * 64)          // 8192 B
#define STAGE_SM  (4 * TILE_SM)       // 32768 B
#define GEMM_SMEM (3 * STAGE_SM)      // 98304 B
#define SWZ(r, c16) ((c16) ^ (((r) >> 1) & 3))

__device__ __forceinline__ void load_stage(
    uint32_t sbase,
    const __nv_bfloat16* __restrict__ Ahi, const __nv_bfloat16* __restrict__ Alo,
    const __nv_bfloat16* __restrict__ Bhi, const __nv_bfloat16* __restrict__ Blo,
    int m0, int n0, int k0, int K, int tid)
{
#pragma unroll
    for (int j = 0; j < 8; j++) {
        const int tile = j >> 1;
        const int cc = tid + (j & 1) * 256;   // 0..511 within tile
        const int row = cc >> 2;
        const int c16 = cc & 3;
        const uint32_t soff = sbase + tile * TILE_SM + row * 64 + (SWZ(row, c16) << 4);
        const __nv_bfloat16* g =
            (tile == 0) ? Ahi : (tile == 1) ? Alo : (tile == 2) ? Bhi : Blo;
        const int grow = (tile < 2) ? (m0 + row) : (n0 + row);
        cp16(soff, g + (size_t)grow * K + k0 + c16 * 8);
    }
}

template <bool EPI>
__global__ __launch_bounds__(256, 2) void gemm_hmma_x3(
    const __nv_bfloat16* __restrict__ Ahi, const __nv_bfloat16* __restrict__ Alo,
    const __nv_bfloat16* __restrict__ Bhi, const __nv_bfloat16* __restrict__ Blo,
    float* __restrict__ C,
    __nv_bfloat16* __restrict__ Qh, __nv_bfloat16* __restrict__ Ql,
    __nv_bfloat16* __restrict__ Kh, __nv_bfloat16* __restrict__ Kl,
    __nv_bfloat16* __restrict__ Vh, __nv_bfloat16* __restrict__ Vl,
    const float* __restrict__ cs, const float* __restrict__ sn,
    int N, int K)
{
    extern __shared__ char smem[];
    const uint32_t sb = smem_u32(smem);
    const int tid = threadIdx.x;
    const int wid = tid >> 5, lane = tid & 31;
    const int wm = wid & 1;
    const int wn = wid >> 1;
    const int lr = lane >> 2;
    const int m0 = blockIdx.y * BM, n0 = blockIdx.x * BN;

    float acc[4][4][4];
#pragma unroll
    for (int mt = 0; mt < 4; mt++)
#pragma unroll
        for (int nt = 0; nt < 4; nt++)
#pragma unroll
            for (int r = 0; r < 4; r++) acc[mt][nt][r] = 0.f;

    const int NIT = K / BK;

    load_stage(sb,            Ahi, Alo, Bhi, Blo, m0, n0, 0,  K, tid);
    CP_COMMIT();
    load_stage(sb + STAGE_SM, Ahi, Alo, Bhi, Blo, m0, n0, BK, K, tid);
    CP_COMMIT();

    // ldmatrix row components
    const int a_row = lane & 15;                         // + c16 hi bit from lane>>4
    const int a_chi = lane >> 4;
    const int b_row = (lane & 7) + ((lane >> 4) << 3);
    const int b_chi = (lane >> 3) & 1;

    for (int it = 0; it < NIT; ++it) {
        CP_WAIT1();            // group(it) drained (always-commit keeps count)
        __syncthreads();       // all warps done compute(it-1) -> buf (it+2)%3 free
        if (it + 2 < NIT)
            load_stage(sb + ((it + 2) % 3) * STAGE_SM,
                       Ahi, Alo, Bhi, Blo, m0, n0, (it + 2) * BK, K, tid);
        CP_COMMIT();           // always commit to keep group counting fixed

        const uint32_t sA = sb + (it % 3) * STAGE_SM;
        const uint32_t sB = sA + 2 * TILE_SM;
#pragma unroll
        for (int kk = 0; kk < 2; kk++) {
            uint32_t ah[4][4], al[4][4], bh[2][4], bl[2][4];
#pragma unroll
            for (int mt = 0; mt < 4; mt++) {
                const int r = wm * 64 + mt * 16 + a_row;
                const int c = kk * 2 + a_chi;
                const uint32_t aaddr = sA + r * 64 + (SWZ(r, c) << 4);
                ldsm_x4(ah[mt], aaddr);
                ldsm_x4(al[mt], aaddr + TILE_SM);
            }
#pragma unroll
            for (int ntp = 0; ntp < 2; ntp++) {
                const int r = wn * 32 + ntp * 16 + b_row;
                const int c = kk * 2 + b_chi;
                const uint32_t baddr = sB + r * 64 + (SWZ(r, c) << 4);
                ldsm_x4(bh[ntp], baddr);
                ldsm_x4(bl[ntp], baddr + TILE_SM);
            }
#pragma unroll
            for (int mt = 0; mt < 4; mt++)
#pragma unroll
                for (int nt = 0; nt < 4; nt++) {
                    const uint32_t* bhf = bh[nt >> 1] + (nt & 1) * 2;
                    const uint32_t* blf = bl[nt >> 1] + (nt & 1) * 2;
                    mma_bf16(acc[mt][nt], ah[mt], bhf);
                    mma_bf16(acc[mt][nt], ah[mt], blf);
                    mma_bf16(acc[mt][nt], al[mt], bhf);
                }
        }
    }

    if (!EPI) {
#pragma unroll
        for (int mt = 0; mt < 4; mt++) {
            const int row = m0 + wm * 64 + mt * 16 + lr;
#pragma unroll
            for (int nt = 0; nt < 4; nt++) {
                const int col = n0 + wn * 32 + nt * 8 + (lane & 3) * 2;
                float2* p0 = (float2*)&C[(size_t)row * N + col];
                float2* p1 = (float2*)&C[(size_t)(row + 8) * N + col];
                *p0 = make_float2(acc[mt][nt][0], acc[mt][nt][1]);
                *p1 = make_float2(acc[mt][nt][2], acc[mt][nt][3]);
            }
        }
    } else {
        __nv_bfloat16 *Dh, *Dl;
        int dstride, coff;
        bool dorope;
        if (n0 < NQ)             { Dh = Qh; Dl = Ql; dstride = NQ;  coff = 0;         dorope = true; }
        else if (n0 < NQ + NKV)  { Dh = Kh; Dl = Kl; dstride = NKV; coff = NQ;        dorope = true; }
        else                     { Dh = Vh; Dl = Vl; dstride = NKV; coff = NQ + NKV;  dorope = false; }
#pragma unroll
        for (int mt = 0; mt < 4; mt++) {
#pragma unroll
            for (int nt = 0; nt < 4; nt++) {
                const int col = n0 + wn * 32 + nt * 8 + (lane & 3) * 2;
                const int fi = (col & 127) >> 1;
#pragma unroll
                for (int r = 0; r < 2; r++) {
                    const int row = m0 + wm * 64 + mt * 16 + lr + 8 * r;
                    float x0 = acc[mt][nt][2 * r];
                    float x1 = acc[mt][nt][2 * r + 1];
                    float y0 = x0, y1 = x1;
                    if (dorope) {
                        const int s = row & (Sv - 1);
                        const float c  = __ldg(cs + s * 64 + fi);
                        const float sv = __ldg(sn + s * 64 + fi);
                        y0 = x0 * c - x1 * sv;
                        y1 = x0 * sv + x1 * c;
                    }
                    uint32_t hw = pack2(y0, y1);
                    __nv_bfloat162 hb = *(__nv_bfloat162*)&hw;
                    uint32_t lw = pack2(y0 - __bfloat162float(hb.x),
                                        y1 - __bfloat162float(hb.y));
                    const size_t o = (size_t)row * dstride + (col - coff);
                    *(uint32_t*)&Dh[o] = hw;
                    *(uint32_t*)&Dl[o] = lw;
                }
            }
        }
    }
}

// ---------------------------------------------------------------------------
// HMMA flash attention (split-bf16 x3, ldmatrix). Unchanged from R6.
// ---------------------------------------------------------------------------
#define FROWB 272
#define FQ_HALF (128 * FROWB)
#define FK_HALF (64 * FROWB)
#define SM_K0   (2 * FQ_HALF)
#define SM_V0   (SM_K0 + 4 * FK_HALF)
#define FLASH_SMEM (SM_V0 + 4 * FK_HALF)

__device__ __forceinline__ void flash_load_kv(
    uint32_t sb, int stage,
    const __nv_bfloat16* __restrict__ Kh, const __nv_bfloat16* __restrict__ Kl,
    const __nv_bfloat16* __restrict__ Vh, const __nv_bfloat16* __restrict__ Vl,
    size_t gbase, int tid)
{
#pragma unroll
    for (int j = 0; j < 16; j++) {
        const int t = j >> 2;
        const int cc = tid + (j & 3) * 256;
        const int row = cc >> 4, c16 = cc & 15;
        const __nv_bfloat16* g = (t == 0) ? Kh : (t == 1) ? Kl : (t == 2) ? Vh : Vl;
        const uint32_t soff = sb + ((t < 2) ? SM_K0 : SM_V0) + stage * 2 * FK_HALF
                              + (t & 1) * FK_HALF + row * FROWB + c16 * 16;
        cp16(soff, g + gbase + (size_t)row * NKV + c16 * 8);
    }
}

__global__ __launch_bounds__(256, 1) void flash_hmma(
    const __nv_bfloat16* __restrict__ Qh_g, const __nv_bfloat16* __restrict__ Ql_g,
    const __nv_bfloat16* __restrict__ Kh_g, const __nv_bfloat16* __restrict__ Kl_g,
    const __nv_bfloat16* __restrict__ Vh_g, const __nv_bfloat16* __restrict__ Vl_g,
    __nv_bfloat16* __restrict__ Oh, __nv_bfloat16* __restrict__ Ol)
{
    extern __shared__ char smem[];
    const uint32_t sb = smem_u32(smem);
    const int tid = threadIdx.x, w = tid >> 5, lane = tid & 31;
    const int lr = lane >> 2, lc = lane & 3;
    const int q0 = blockIdx.x * 128, h = blockIdx.y, b = blockIdx.z;
    const int kvh = h >> 2;
    const float scale = 0.08838834764831845f;

    {
        const size_t gq = ((size_t)(b * Sv + q0)) * NQ + h * HDv;
#pragma unroll
        for (int j = 0; j < 16; j++) {
            const int hl = j >> 3;
            const int cc = tid + (j & 7) * 256;
            const int row = cc >> 4, c16 = cc & 15;
            const __nv_bfloat16* g = hl ? Ql_g : Qh_g;
            cp16(sb + hl * FQ_HALF + row * FROWB + c16 * 16,
                 g + gq + (size_t)row * NQ + c16 * 8);
        }
    }
    const int ktmax = 2 * blockIdx.x + 1;
    flash_load_kv(sb, 0, Kh_g, Kl_g, Vh_g, Vl_g,
                  ((size_t)(b * Sv)) * NKV + kvh * HDv, tid);
    CP_COMMIT();

    float o[16][4];
#pragma unroll
    for (int i = 0; i < 16; i++)
#pragma unroll
        for (int j = 0; j < 4; j++) o[i][j] = 0.f;
    float mrow[2] = {-1e30f, -1e30f};
    float lrow[2] = {0.f, 0.f};

    const int a_row = lane & 15;
    const int a_cb  = (lane >> 4) << 4;
    const int b_row = (lane & 7) + ((lane >> 4) << 3);
    const int b_cb  = ((lane >> 3) & 1) << 4;

    for (int kt = 0; kt <= ktmax; ++kt) {
        CP_WAIT0();
        __syncthreads();
        if (kt < ktmax) {
            flash_load_kv(sb, (kt + 1) & 1, Kh_g, Kl_g, Vh_g, Vl_g,
                          ((size_t)(b * Sv + (kt + 1) * 64)) * NKV + kvh * HDv, tid);
            CP_COMMIT();
        }

        const int k0 = kt * 64;
        if (k0 > q0 + w * 16 + 15) continue;

        const uint32_t Kst = sb + SM_K0 + (kt & 1) * 2 * FK_HALF;
        const uint32_t Vst = sb + SM_V0 + (kt & 1) * 2 * FK_HALF;

        float s[8][4];
#pragma unroll
        for (int nf = 0; nf < 8; nf++)
#pragma unroll
            for (int r = 0; r < 4; r++) s[nf][r] = 0.f;

#pragma unroll
        for (int kf = 0; kf < 8; kf++) {
            const uint32_t qaddr = sb + (w * 16 + a_row) * FROWB + kf * 32 + a_cb;
            uint32_t ah[4], al[4];
            ldsm_x4(ah, qaddr);
            ldsm_x4(al, qaddr + FQ_HALF);
#pragma unroll
            for (int nfp = 0; nfp < 4; nfp++) {
                const uint32_t kaddr = Kst + (nfp * 16 + b_row) * FROWB + kf * 32 + b_cb;
                uint32_t bh4[4], bl4[4];
                ldsm_x4(bh4, kaddr);
                ldsm_x4(bl4, kaddr + FK_HALF);
                mma_bf16(s[2 * nfp],     ah, bh4);
                mma_bf16(s[2 * nfp],     ah, bl4);
                mma_bf16(s[2 * nfp],     al, bh4);
                mma_bf16(s[2 * nfp + 1], ah, bh4 + 2);
                mma_bf16(s[2 * nfp + 1], ah, bl4 + 2);
                mma_bf16(s[2 * nfp + 1], al, bh4 + 2);
            }
        }

        const bool diag = (k0 + 63 > q0 + w * 16);
#pragma unroll
        for (int r = 0; r < 2; r++) {
            const int qrow = q0 + w * 16 + lr + 8 * r;
            float mx = -1e30f;
#pragma unroll
            for (int nf = 0; nf < 8; nf++) {
                float v0 = s[nf][2 * r] * scale;
                float v1 = s[nf][2 * r + 1] * scale;
                if (diag) {
                    const int col = k0 + nf * 8 + lc * 2;
                    if (col > qrow) v0 = -1e30f;
                    if (col + 1 > qrow) v1 = -1e30f;
                }
                s[nf][2 * r] = v0;
                s[nf][2 * r + 1] = v1;
                mx = fmaxf(mx, fmaxf(v0, v1));
            }
            mx = fmaxf(mx, __shfl_xor_sync(0xffffffffu, mx, 1));
            mx = fmaxf(mx, __shfl_xor_sync(0xffffffffu, mx, 2));
            const float m_new = fmaxf(mrow[r], mx);
            const float alpha = __expf(mrow[r] - m_new);
            mrow[r] = m_new;
            float sum = 0.f;
#pragma unroll
            for (int nf = 0; nf < 8; nf++) {
                float p0 = __expf(s[nf][2 * r] - m_new);
                float p1 = __expf(s[nf][2 * r + 1] - m_new);
                s[nf][2 * r] = p0;
                s[nf][2 * r + 1] = p1;
                sum += p0 + p1;
            }
            sum += __shfl_xor_sync(0xffffffffu, sum, 1);
            sum += __shfl_xor_sync(0xffffffffu, sum, 2);
            lrow[r] = lrow[r] * alpha + sum;
#pragma unroll
            for (int nf2 = 0; nf2 < 16; nf2++) {
                o[nf2][2 * r] *= alpha;
                o[nf2][2 * r + 1] *= alpha;
            }
        }

        uint32_t phi[4][4], plo[4][4];
#pragma unroll
        for (int kf2 = 0; kf2 < 4; kf2++) {
#pragma unroll
            for (int m = 0; m < 2; m++) {
                const int nf = 2 * kf2 + m;
                float x0 = s[nf][0], x1 = s[nf][1], x2 = s[nf][2], x3 = s[nf][3];
                uint32_t h01 = pack2(x0, x1), h23 = pack2(x2, x3);
                phi[kf2][2 * m]     = h01;
                phi[kf2][2 * m + 1] = h23;
                __nv_bfloat162 b01 = *(__nv_bfloat162*)&h01;
                __nv_bfloat162 b23 = *(__nv_bfloat162*)&h23;
                plo[kf2][2 * m]     = pack2(x0 - __bfloat162float(b01.x),
                                            x1 - __bfloat162float(b01.y));
                plo[kf2][2 * m + 1] = pack2(x2 - __bfloat162float(b23.x),
                                            x3 - __bfloat162float(b23.y));
            }
        }

#pragma unroll
        for (int kf2 = 0; kf2 < 4; kf2++) {
#pragma unroll
            for (int nfp = 0; nfp < 8; nfp++) {
                const uint32_t va = Vst + (kf2 * 16 + (lane & 15)) * FROWB
                                    + (nfp * 16 + ((lane >> 4) << 3)) * 2;
                uint32_t bh4[4], bl4[4];
                ldsm_x4_t(bh4, va);
                ldsm_x4_t(bl4, va + FK_HALF);
                mma_bf16(o[2 * nfp],     phi[kf2], bh4);
                mma_bf16(o[2 * nfp],     phi[kf2], bl4);
                mma_bf16(o[2 * nfp],     plo[kf2], bh4);
                mma_bf16(o[2 * nfp + 1], phi[kf2], bh4 + 2);
                mma_bf16(o[2 * nfp + 1], phi[kf2], bl4 + 2);
                mma_bf16(o[2 * nfp + 1], plo[kf2], bh4 + 2);
            }
        }
    }

#pragma unroll
    for (int r = 0; r < 2; r++) {
        const float inv = 1.f / lrow[r];
        const int row = q0 + w * 16 + lr + 8 * r;
        const size_t base = ((size_t)(b * Sv + row)) * NQ + h * HDv + lc * 2;
#pragma unroll
        for (int nf2 = 0; nf2 < 16; nf2++) {
            float y0 = o[nf2][2 * r] * inv;
            float y1 = o[nf2][2 * r + 1] * inv;
            uint32_t hw = pack2(y0, y1);
            __nv_bfloat162 hb = *(__nv_bfloat162*)&hw;
            uint32_t lw = pack2(y0 - __bfloat162float(hb.x),
                                y1 - __bfloat162float(hb.y));
            *(uint32_t*)&Oh[base + nf2 * 8] = hw;
            *(uint32_t*)&Ol[base + nf2 * 8] = lw;
        }
    }
}

// ---------------------------------------------------------------------------
// Launch. Inputs: 0=x 1=cos 2=sin 3=positions 4=mask 5=wq 6=wk 7=wv 8=wo
// ---------------------------------------------------------------------------
extern "C" void kernel_launch(void* const* d_in, const int* in_sizes, int n_in,
                              void* d_out, int out_size)
{
    const float* x  = (const float*)d_in[0];
    const float* fc = (const float*)d_in[1];
    const float* fs = (const float*)d_in[2];
    const float* wq = (const float*)d_in[5];
    const float* wk = (const float*)d_in[6];
    const float* wv = (const float*)d_in[7];
    const float* wo = (const float*)d_in[8];
    float* out = (float*)d_out;

    __nv_bfloat16 *xh, *xl, *wh, *wl, *oh, *ol, *ah, *al;
    __nv_bfloat16 *qrh, *qrl, *krh, *krl, *vsh, *vsl;
    cudaGetSymbolAddress((void**)&xh, g_x_hi);    cudaGetSymbolAddress((void**)&xl, g_x_lo);
    cudaGetSymbolAddress((void**)&wh, g_wqkv_hi); cudaGetSymbolAddress((void**)&wl, g_wqkv_lo);
    cudaGetSymbolAddress((void**)&oh, g_wo_hi);   cudaGetSymbolAddress((void**)&ol, g_wo_lo);
    cudaGetSymbolAddress((void**)&ah, g_at_hi);   cudaGetSymbolAddress((void**)&al, g_at_lo);
    cudaGetSymbolAddress((void**)&qrh, g_qr_hi);  cudaGetSymbolAddress((void**)&qrl, g_qr_lo);
    cudaGetSymbolAddress((void**)&krh, g_kr_hi);  cudaGetSymbolAddress((void**)&krl, g_kr_lo);
    cudaGetSymbolAddress((void**)&vsh, g_vs_hi);  cudaGetSymbolAddress((void**)&vsl, g_vs_lo);

    // split conversions (weights concatenated into g_wqkv)
    {
        long n4;
        n4 = (long)Mv * Dv / 4;
        cvt_split<<<(unsigned)((n4 + 255) / 256), 256>>>(x, xh, xl, n4);
        n4 = (long)NQ * Dv / 4;
        cvt_split<<<(unsigned)((n4 + 255) / 256), 256>>>(wq, wh, wl, n4);
        n4 = (long)NKV * Dv / 4;
        cvt_split<<<(unsigned)((n4 + 255) / 256), 256>>>(
            wk, wh + (size_t)NQ * Dv, wl + (size_t)NQ * Dv, n4);
        cvt_split<<<(unsigned)((n4 + 255) / 256), 256>>>(
            wv, wh + (size_t)(NQ + NKV) * Dv, wl + (size_t)(NQ + NKV) * Dv, n4);
        n4 = (long)Dv * NQ / 4;
        cvt_split<<<(unsigned)((n4 + 255) / 256), 256>>>(wo, oh, ol, n4);
    }

    cudaFuncSetAttribute(gemm_hmma_x3<true>,
                         cudaFuncAttributeMaxDynamicSharedMemorySize, GEMM_SMEM);
    cudaFuncSetAttribute(gemm_hmma_x3<false>,
                         cudaFuncAttributeMaxDynamicSharedMemorySize, GEMM_SMEM);

    // Fused QKV projection + RoPE + split
    gemm_hmma_x3<true><<<dim3(NQKV / BN, Mv / BM), 256, GEMM_SMEM>>>(
        xh, xl, wh, wl, nullptr,
        qrh, qrl, krh, krl, vsh, vsl, fc, fs, NQKV, Dv);

    // HMMA flash attention (writes split bf16 directly)
    cudaFuncSetAttribute(flash_hmma, cudaFuncAttributeMaxDynamicSharedMemorySize, FLASH_SMEM);
    flash_hmma<<<dim3(Sv / 128, Hv, Bv), 256, FLASH_SMEM>>>(
        qrh, qrl, krh, krl, vsh, vsl, ah, al);

    // Output projection
    gemm_hmma_x3<false><<<dim3(NQ / BN, Mv / BM), 256, GEMM_SMEM>>>(
        ah, al, oh, ol, out,
        nullptr, nullptr, nullptr, nullptr, nullptr, nullptr, nullptr, nullptr,
        NQ, Dv);
}

// round 8
// speedup vs baseline: 3.9795x; 1.0035x over previous
#include <cuda_runtime.h>
#include <cuda_bf16.h>
#include <cstdint>
#include <math.h>

// Problem constants
#define Bv   2
#define Sv   2048
#define Dv   4096
#define Hv   32
#define KVHv 8
#define HDv  128
#define Mv   (Bv * Sv)       // 4096
#define NQ   (Hv * HDv)      // 4096
#define NKV  (KVHv * HDv)    // 1024
#define NQKV (NQ + 2 * NKV)  // 6144

// bf16 split-precision scratch
__device__ __nv_bfloat16 g_x_hi[(size_t)Mv * Dv],    g_x_lo[(size_t)Mv * Dv];
__device__ __nv_bfloat16 g_wqkv_hi[(size_t)NQKV * Dv], g_wqkv_lo[(size_t)NQKV * Dv];
__device__ __nv_bfloat16 g_wo_hi[(size_t)Dv * NQ],   g_wo_lo[(size_t)Dv * NQ];
__device__ __nv_bfloat16 g_at_hi[(size_t)Mv * NQ],   g_at_lo[(size_t)Mv * NQ];
// rope'd / split Q,K,V for flash
__device__ __nv_bfloat16 g_qr_hi[(size_t)Mv * NQ],  g_qr_lo[(size_t)Mv * NQ];
__device__ __nv_bfloat16 g_kr_hi[(size_t)Mv * NKV], g_kr_lo[(size_t)Mv * NKV];
__device__ __nv_bfloat16 g_vs_hi[(size_t)Mv * NKV], g_vs_lo[(size_t)Mv * NKV];

// ---------------------------------------------------------------------------
// Helpers (compute_103-safe)
// ---------------------------------------------------------------------------
__device__ __forceinline__ uint32_t smem_u32(const void* p) {
    uint32_t a;
    asm("{ .reg .u64 t; cvta.to.shared.u64 t, %1; cvt.u32.u64 %0, t; }" : "=r"(a) : "l"(p));
    return a;
}
__device__ __forceinline__ void cp16(uint32_t dst, const void* src) {
    asm volatile("cp.async.cg.shared.global [%0], [%1], 16;" :: "r"(dst), "l"(src));
}
#define CP_COMMIT() asm volatile("cp.async.commit_group;" ::: "memory")
#define CP_WAIT1()  asm volatile("cp.async.wait_group 1;" ::: "memory")
#define CP_WAIT0()  asm volatile("cp.async.wait_group 0;" ::: "memory")

__device__ __forceinline__ void mma_bf16(float* c, const uint32_t* a, const uint32_t* b) {
    asm volatile("mma.sync.aligned.m16n8k16.row.col.f32.bf16.bf16.f32 "
        "{%0,%1,%2,%3}, {%4,%5,%6,%7}, {%8,%9}, {%0,%1,%2,%3};"
        : "+f"(c[0]), "+f"(c[1]), "+f"(c[2]), "+f"(c[3])
        : "r"(a[0]), "r"(a[1]), "r"(a[2]), "r"(a[3]), "r"(b[0]), "r"(b[1]));
}
__device__ __forceinline__ void ldsm_x4(uint32_t* r, uint32_t addr) {
    asm volatile("ldmatrix.sync.aligned.m8n8.x4.shared.b16 {%0,%1,%2,%3}, [%4];"
        : "=r"(r[0]), "=r"(r[1]), "=r"(r[2]), "=r"(r[3]) : "r"(addr));
}
__device__ __forceinline__ void ldsm_x4_t(uint32_t* r, uint32_t addr) {
    asm volatile("ldmatrix.sync.aligned.m8n8.x4.trans.shared.b16 {%0,%1,%2,%3}, [%4];"
        : "=r"(r[0]), "=r"(r[1]), "=r"(r[2]), "=r"(r[3]) : "r"(addr));
}
__device__ __forceinline__ uint32_t pack2(float x, float y) {
    __nv_bfloat162 t = __floats2bfloat162_rn(x, y);
    return *(uint32_t*)&t;
}

// ---------------------------------------------------------------------------
// Split fp32 -> bf16 hi/lo
// ---------------------------------------------------------------------------
__global__ void cvt_split(const float* __restrict__ in,
                          __nv_bfloat16* __restrict__ hi,
                          __nv_bfloat16* __restrict__ lo, long n4) {
    long i = (long)blockIdx.x * blockDim.x + threadIdx.x;
    if (i >= n4) return;
    float4 v = ((const float4*)in)[i];
    __nv_bfloat16 h[4], l[4];
    float vv[4] = {v.x, v.y, v.z, v.w};
#pragma unroll
    for (int j = 0; j < 4; j++) {
        h[j] = __float2bfloat16(vv[j]);
        l[j] = __float2bfloat16(vv[j] - __bfloat162float(h[j]));
    }
    ((__nv_bfloat162*)hi)[i * 2]     = __nv_bfloat162(h[0], h[1]);
    ((__nv_bfloat162*)hi)[i * 2 + 1] = __nv_bfloat162(h[2], h[3]);
    ((__nv_bfloat162*)lo)[i * 2]     = __nv_bfloat162(l[0], l[1]);
    ((__nv_bfloat162*)lo)[i * 2 + 1] = __nv_bfloat162(l[2], l[3]);
}

// ---------------------------------------------------------------------------
// HMMA bf16x3 GEMM, 3-stage pipeline, 96KB smem, 2 CTAs/SM. (unchanged R7)
// ---------------------------------------------------------------------------
#define BM 128
#define BN 128
#define BK 32
#define TILE_SM   (128 * 64)          // 8192 B
#define STAGE_SM  (4 * TILE_SM)       // 32768 B
#define GEMM_SMEM (3 * STAGE_SM)      // 98304 B
#define SWZ(r, c16) ((c16) ^ (((r) >> 1) & 3))

__device__ __forceinline__ void load_stage(
    uint32_t sbase,
    const __nv_bfloat16* __restrict__ Ahi, const __nv_bfloat16* __restrict__ Alo,
    const __nv_bfloat16* __restrict__ Bhi, const __nv_bfloat16* __restrict__ Blo,
    int m0, int n0, int k0, int K, int tid)
{
#pragma unroll
    for (int j = 0; j < 8; j++) {
        const int tile = j >> 1;
        const int cc = tid + (j & 1) * 256;
        const int row = cc >> 2;
        const int c16 = cc & 3;
        const uint32_t soff = sbase + tile * TILE_SM + row * 64 + (SWZ(row, c16) << 4);
        const __nv_bfloat16* g =
            (tile == 0) ? Ahi : (tile == 1) ? Alo : (tile == 2) ? Bhi : Blo;
        const int grow = (tile < 2) ? (m0 + row) : (n0 + row);
        cp16(soff, g + (size_t)grow * K + k0 + c16 * 8);
    }
}

template <bool EPI>
__global__ __launch_bounds__(256, 2) void gemm_hmma_x3(
    const __nv_bfloat16* __restrict__ Ahi, const __nv_bfloat16* __restrict__ Alo,
    const __nv_bfloat16* __restrict__ Bhi, const __nv_bfloat16* __restrict__ Blo,
    float* __restrict__ C,
    __nv_bfloat16* __restrict__ Qh, __nv_bfloat16* __restrict__ Ql,
    __nv_bfloat16* __restrict__ Kh, __nv_bfloat16* __restrict__ Kl,
    __nv_bfloat16* __restrict__ Vh, __nv_bfloat16* __restrict__ Vl,
    const float* __restrict__ cs, const float* __restrict__ sn,
    int N, int K)
{
    extern __shared__ char smem[];
    const uint32_t sb = smem_u32(smem);
    const int tid = threadIdx.x;
    const int wid = tid >> 5, lane = tid & 31;
    const int wm = wid & 1;
    const int wn = wid >> 1;
    const int lr = lane >> 2;
    const int m0 = blockIdx.y * BM, n0 = blockIdx.x * BN;

    float acc[4][4][4];
#pragma unroll
    for (int mt = 0; mt < 4; mt++)
#pragma unroll
        for (int nt = 0; nt < 4; nt++)
#pragma unroll
            for (int r = 0; r < 4; r++) acc[mt][nt][r] = 0.f;

    const int NIT = K / BK;

    load_stage(sb,            Ahi, Alo, Bhi, Blo, m0, n0, 0,  K, tid);
    CP_COMMIT();
    load_stage(sb + STAGE_SM, Ahi, Alo, Bhi, Blo, m0, n0, BK, K, tid);
    CP_COMMIT();

    const int a_row = lane & 15;
    const int a_chi = lane >> 4;
    const int b_row = (lane & 7) + ((lane >> 4) << 3);
    const int b_chi = (lane >> 3) & 1;

    for (int it = 0; it < NIT; ++it) {
        CP_WAIT1();
        __syncthreads();
        if (it + 2 < NIT)
            load_stage(sb + ((it + 2) % 3) * STAGE_SM,
                       Ahi, Alo, Bhi, Blo, m0, n0, (it + 2) * BK, K, tid);
        CP_COMMIT();

        const uint32_t sA = sb + (it % 3) * STAGE_SM;
        const uint32_t sB = sA + 2 * TILE_SM;
#pragma unroll
        for (int kk = 0; kk < 2; kk++) {
            uint32_t ah[4][4], al[4][4], bh[2][4], bl[2][4];
#pragma unroll
            for (int mt = 0; mt < 4; mt++) {
                const int r = wm * 64 + mt * 16 + a_row;
                const int c = kk * 2 + a_chi;
                const uint32_t aaddr = sA + r * 64 + (SWZ(r, c) << 4);
                ldsm_x4(ah[mt], aaddr);
                ldsm_x4(al[mt], aaddr + TILE_SM);
            }
#pragma unroll
            for (int ntp = 0; ntp < 2; ntp++) {
                const int r = wn * 32 + ntp * 16 + b_row;
                const int c = kk * 2 + b_chi;
                const uint32_t baddr = sB + r * 64 + (SWZ(r, c) << 4);
                ldsm_x4(bh[ntp], baddr);
                ldsm_x4(bl[ntp], baddr + TILE_SM);
            }
#pragma unroll
            for (int mt = 0; mt < 4; mt++)
#pragma unroll
                for (int nt = 0; nt < 4; nt++) {
                    const uint32_t* bhf = bh[nt >> 1] + (nt & 1) * 2;
                    const uint32_t* blf = bl[nt >> 1] + (nt & 1) * 2;
                    mma_bf16(acc[mt][nt], ah[mt], bhf);
                    mma_bf16(acc[mt][nt], ah[mt], blf);
                    mma_bf16(acc[mt][nt], al[mt], bhf);
                }
        }
    }

    if (!EPI) {
#pragma unroll
        for (int mt = 0; mt < 4; mt++) {
            const int row = m0 + wm * 64 + mt * 16 + lr;
#pragma unroll
            for (int nt = 0; nt < 4; nt++) {
                const int col = n0 + wn * 32 + nt * 8 + (lane & 3) * 2;
                float2* p0 = (float2*)&C[(size_t)row * N + col];
                float2* p1 = (float2*)&C[(size_t)(row + 8) * N + col];
                *p0 = make_float2(acc[mt][nt][0], acc[mt][nt][1]);
                *p1 = make_float2(acc[mt][nt][2], acc[mt][nt][3]);
            }
        }
    } else {
        __nv_bfloat16 *Dh, *Dl;
        int dstride, coff;
        bool dorope;
        if (n0 < NQ)             { Dh = Qh; Dl = Ql; dstride = NQ;  coff = 0;         dorope = true; }
        else if (n0 < NQ + NKV)  { Dh = Kh; Dl = Kl; dstride = NKV; coff = NQ;        dorope = true; }
        else                     { Dh = Vh; Dl = Vl; dstride = NKV; coff = NQ + NKV;  dorope = false; }
#pragma unroll
        for (int mt = 0; mt < 4; mt++) {
#pragma unroll
            for (int nt = 0; nt < 4; nt++) {
                const int col = n0 + wn * 32 + nt * 8 + (lane & 3) * 2;
                const int fi = (col & 127) >> 1;
#pragma unroll
                for (int r = 0; r < 2; r++) {
                    const int row = m0 + wm * 64 + mt * 16 + lr + 8 * r;
                    float x0 = acc[mt][nt][2 * r];
                    float x1 = acc[mt][nt][2 * r + 1];
                    float y0 = x0, y1 = x1;
                    if (dorope) {
                        const int s = row & (Sv - 1);
                        const float c  = __ldg(cs + s * 64 + fi);
                        const float sv = __ldg(sn + s * 64 + fi);
                        y0 = x0 * c - x1 * sv;
                        y1 = x0 * sv + x1 * c;
                    }
                    uint32_t hw = pack2(y0, y1);
                    __nv_bfloat162 hb = *(__nv_bfloat162*)&hw;
                    uint32_t lw = pack2(y0 - __bfloat162float(hb.x),
                                        y1 - __bfloat162float(hb.y));
                    const size_t o = (size_t)row * dstride + (col - coff);
                    *(uint32_t*)&Dh[o] = hw;
                    *(uint32_t*)&Dl[o] = lw;
                }
            }
        }
    }
}

// ---------------------------------------------------------------------------
// HMMA flash attention v2: 2 CTAs/SM.
// CTA = 64 q-rows, 128 threads (4 warps x 16 rows), K/V tiles of 32 rows
// double-buffered, Q fragments register-resident. 104 KB smem.
// ---------------------------------------------------------------------------
#define FROWB 272
#define FQ_HALF (64 * FROWB)          // 17408
#define FK_HALF (32 * FROWB)          // 8704
#define SM_KV   (2 * FQ_HALF)         // 34816
#define KV_STAGE (4 * FK_HALF)        // 34816 (Khi,Klo,Vhi,Vlo)
#define FLASH_SMEM (SM_KV + 2 * KV_STAGE)   // 104448

__device__ __forceinline__ void flash_load_kv(
    uint32_t sb, int stage,
    const __nv_bfloat16* __restrict__ Kh, const __nv_bfloat16* __restrict__ Kl,
    const __nv_bfloat16* __restrict__ Vh, const __nv_bfloat16* __restrict__ Vl,
    size_t gbase, int tid)
{
#pragma unroll
    for (int j = 0; j < 16; j++) {
        const int t = j >> 2;                 // 0:Kh 1:Kl 2:Vh 3:Vl
        const int cc = tid + (j & 3) * 128;   // 0..511
        const int row = cc >> 4, c16 = cc & 15;
        const __nv_bfloat16* g = (t == 0) ? Kh : (t == 1) ? Kl : (t == 2) ? Vh : Vl;
        const uint32_t soff = sb + SM_KV + stage * KV_STAGE + t * FK_HALF
                              + row * FROWB + c16 * 16;
        cp16(soff, g + gbase + (size_t)row * NKV + c16 * 8);
    }
}

__global__ __launch_bounds__(128, 2) void flash_hmma(
    const __nv_bfloat16* __restrict__ Qh_g, const __nv_bfloat16* __restrict__ Ql_g,
    const __nv_bfloat16* __restrict__ Kh_g, const __nv_bfloat16* __restrict__ Kl_g,
    const __nv_bfloat16* __restrict__ Vh_g, const __nv_bfloat16* __restrict__ Vl_g,
    __nv_bfloat16* __restrict__ Oh, __nv_bfloat16* __restrict__ Ol)
{
    extern __shared__ char smem[];
    const uint32_t sb = smem_u32(smem);
    const int tid = threadIdx.x, w = tid >> 5, lane = tid & 31;
    const int lr = lane >> 2, lc = lane & 3;
    const int q0 = blockIdx.x * 64, h = blockIdx.y, b = blockIdx.z;
    const int kvh = h >> 2;
    const float scale = 0.08838834764831845f;

    // Stage Q (hi/lo)
    {
        const size_t gq = ((size_t)(b * Sv + q0)) * NQ + h * HDv;
#pragma unroll
        for (int j = 0; j < 16; j++) {
            const int hl = j >> 3;
            const int cc = tid + (j & 7) * 128;   // 0..1023
            const int row = cc >> 4, c16 = cc & 15;
            const __nv_bfloat16* g = hl ? Ql_g : Qh_g;
            cp16(sb + hl * FQ_HALF + row * FROWB + c16 * 16,
                 g + gq + (size_t)row * NQ + c16 * 8);
        }
    }
    CP_COMMIT();
    flash_load_kv(sb, 0, Kh_g, Kl_g, Vh_g, Vl_g,
                  ((size_t)(b * Sv)) * NKV + kvh * HDv, tid);
    CP_COMMIT();

    const int a_row = lane & 15;
    const int a_cb  = (lane >> 4) << 4;
    const int b_row = (lane & 7) + ((lane >> 4) << 3);
    const int b_cb  = ((lane >> 3) & 1) << 4;

    // Q fragments -> registers (once)
    CP_WAIT1();
    __syncthreads();
    uint32_t qh[8][4], ql[8][4];
#pragma unroll
    for (int kf = 0; kf < 8; kf++) {
        const uint32_t qaddr = sb + (w * 16 + a_row) * FROWB + kf * 32 + a_cb;
        ldsm_x4(qh[kf], qaddr);
        ldsm_x4(ql[kf], qaddr + FQ_HALF);
    }

    float o[16][4];
#pragma unroll
    for (int i = 0; i < 16; i++)
#pragma unroll
        for (int j = 0; j < 4; j++) o[i][j] = 0.f;
    float mrow[2] = {-1e30f, -1e30f};
    float lrow[2] = {0.f, 0.f};

    const int ktmax = 2 * blockIdx.x + 1;
    for (int kt = 0; kt <= ktmax; ++kt) {
        CP_WAIT0();
        __syncthreads();
        if (kt < ktmax) {
            flash_load_kv(sb, (kt + 1) & 1, Kh_g, Kl_g, Vh_g, Vl_g,
                          ((size_t)(b * Sv + (kt + 1) * 32)) * NKV + kvh * HDv, tid);
            CP_COMMIT();
        }

        const int k0 = kt * 32;
        if (k0 > q0 + w * 16 + 15) continue;   // fully masked for this warp

        const uint32_t Kst = sb + SM_KV + (kt & 1) * KV_STAGE;
        const uint32_t Vst = Kst + 2 * FK_HALF;

        // ---- S = Q K^T (3-pass split; Q from registers) ----
        float s[4][4];
#pragma unroll
        for (int nf = 0; nf < 4; nf++)
#pragma unroll
            for (int r = 0; r < 4; r++) s[nf][r] = 0.f;

#pragma unroll
        for (int kf = 0; kf < 8; kf++) {
#pragma unroll
            for (int nfp = 0; nfp < 2; nfp++) {
                const uint32_t kaddr = Kst + (nfp * 16 + b_row) * FROWB + kf * 32 + b_cb;
                uint32_t bh4[4], bl4[4];
                ldsm_x4(bh4, kaddr);
                ldsm_x4(bl4, kaddr + FK_HALF);
                mma_bf16(s[2 * nfp],     qh[kf], bh4);
                mma_bf16(s[2 * nfp],     qh[kf], bl4);
                mma_bf16(s[2 * nfp],     ql[kf], bh4);
                mma_bf16(s[2 * nfp + 1], qh[kf], bh4 + 2);
                mma_bf16(s[2 * nfp + 1], qh[kf], bl4 + 2);
                mma_bf16(s[2 * nfp + 1], ql[kf], bh4 + 2);
            }
        }

        // ---- scale + causal mask + online softmax ----
        const bool diag = (k0 + 31 > q0 + w * 16);
#pragma unroll
        for (int r = 0; r < 2; r++) {
            const int qrow = q0 + w * 16 + lr + 8 * r;
            float mx = -1e30f;
#pragma unroll
            for (int nf = 0; nf < 4; nf++) {
                float v0 = s[nf][2 * r] * scale;
                float v1 = s[nf][2 * r + 1] * scale;
                if (diag) {
                    const int col = k0 + nf * 8 + lc * 2;
                    if (col > qrow) v0 = -1e30f;
                    if (col + 1 > qrow) v1 = -1e30f;
                }
                s[nf][2 * r] = v0;
                s[nf][2 * r + 1] = v1;
                mx = fmaxf(mx, fmaxf(v0, v1));
            }
            mx = fmaxf(mx, __shfl_xor_sync(0xffffffffu, mx, 1));
            mx = fmaxf(mx, __shfl_xor_sync(0xffffffffu, mx, 2));
            const float m_new = fmaxf(mrow[r], mx);
            const float alpha = __expf(mrow[r] - m_new);
            mrow[r] = m_new;
            float sum = 0.f;
#pragma unroll
            for (int nf = 0; nf < 4; nf++) {
                float p0 = __expf(s[nf][2 * r] - m_new);
                float p1 = __expf(s[nf][2 * r + 1] - m_new);
                s[nf][2 * r] = p0;
                s[nf][2 * r + 1] = p1;
                sum += p0 + p1;
            }
            sum += __shfl_xor_sync(0xffffffffu, sum, 1);
            sum += __shfl_xor_sync(0xffffffffu, sum, 2);
            lrow[r] = lrow[r] * alpha + sum;
#pragma unroll
            for (int nf2 = 0; nf2 < 16; nf2++) {
                o[nf2][2 * r] *= alpha;
                o[nf2][2 * r + 1] *= alpha;
            }
        }

        // ---- split P into hi/lo A-fragments (register-only) ----
        uint32_t phi[2][4], plo[2][4];
#pragma unroll
        for (int kf2 = 0; kf2 < 2; kf2++) {
#pragma unroll
            for (int m = 0; m < 2; m++) {
                const int nf = 2 * kf2 + m;
                float x0 = s[nf][0], x1 = s[nf][1], x2 = s[nf][2], x3 = s[nf][3];
                uint32_t h01 = pack2(x0, x1), h23 = pack2(x2, x3);
                phi[kf2][2 * m]     = h01;
                phi[kf2][2 * m + 1] = h23;
                __nv_bfloat162 b01 = *(__nv_bfloat162*)&h01;
                __nv_bfloat162 b23 = *(__nv_bfloat162*)&h23;
                plo[kf2][2 * m]     = pack2(x0 - __bfloat162float(b01.x),
                                            x1 - __bfloat162float(b01.y));
                plo[kf2][2 * m + 1] = pack2(x2 - __bfloat162float(b23.x),
                                            x3 - __bfloat162float(b23.y));
            }
        }

        // ---- O += P V (3-pass split), V via ldmatrix.trans ----
#pragma unroll
        for (int kf2 = 0; kf2 < 2; kf2++) {
#pragma unroll
            for (int nfp = 0; nfp < 8; nfp++) {
                const uint32_t va = Vst + (kf2 * 16 + (lane & 15)) * FROWB
                                    + (nfp * 16 + ((lane >> 4) << 3)) * 2;
                uint32_t bh4[4], bl4[4];
                ldsm_x4_t(bh4, va);
                ldsm_x4_t(bl4, va + FK_HALF);
                mma_bf16(o[2 * nfp],     phi[kf2], bh4);
                mma_bf16(o[2 * nfp],     phi[kf2], bl4);
                mma_bf16(o[2 * nfp],     plo[kf2], bh4);
                mma_bf16(o[2 * nfp + 1], phi[kf2], bh4 + 2);
                mma_bf16(o[2 * nfp + 1], phi[kf2], bl4 + 2);
                mma_bf16(o[2 * nfp + 1], plo[kf2], bh4 + 2);
            }
        }
    }

    // ---- epilogue: write split bf16 hi/lo ----
#pragma unroll
    for (int r = 0; r < 2; r++) {
        const float inv = 1.f / lrow[r];
        const int row = q0 + w * 16 + lr + 8 * r;
        const size_t base = ((size_t)(b * Sv + row)) * NQ + h * HDv + lc * 2;
#pragma unroll
        for (int nf2 = 0; nf2 < 16; nf2++) {
            float y0 = o[nf2][2 * r] * inv;
            float y1 = o[nf2][2 * r + 1] * inv;
            uint32_t hw = pack2(y0, y1);
            __nv_bfloat162 hb = *(__nv_bfloat162*)&hw;
            uint32_t lw = pack2(y0 - __bfloat162float(hb.x),
                                y1 - __bfloat162float(hb.y));
            *(uint32_t*)&Oh[base + nf2 * 8] = hw;
            *(uint32_t*)&Ol[base + nf2 * 8] = lw;
        }
    }
}

// ---------------------------------------------------------------------------
// Launch. Inputs: 0=x 1=cos 2=sin 3=positions 4=mask 5=wq 6=wk 7=wv 8=wo
// ---------------------------------------------------------------------------
extern "C" void kernel_launch(void* const* d_in, const int* in_sizes, int n_in,
                              void* d_out, int out_size)
{
    const float* x  = (const float*)d_in[0];
    const float* fc = (const float*)d_in[1];
    const float* fs = (const float*)d_in[2];
    const float* wq = (const float*)d_in[5];
    const float* wk = (const float*)d_in[6];
    const float* wv = (const float*)d_in[7];
    const float* wo = (const float*)d_in[8];
    float* out = (float*)d_out;

    __nv_bfloat16 *xh, *xl, *wh, *wl, *oh, *ol, *ah, *al;
    __nv_bfloat16 *qrh, *qrl, *krh, *krl, *vsh, *vsl;
    cudaGetSymbolAddress((void**)&xh, g_x_hi);    cudaGetSymbolAddress((void**)&xl, g_x_lo);
    cudaGetSymbolAddress((void**)&wh, g_wqkv_hi); cudaGetSymbolAddress((void**)&wl, g_wqkv_lo);
    cudaGetSymbolAddress((void**)&oh, g_wo_hi);   cudaGetSymbolAddress((void**)&ol, g_wo_lo);
    cudaGetSymbolAddress((void**)&ah, g_at_hi);   cudaGetSymbolAddress((void**)&al, g_at_lo);
    cudaGetSymbolAddress((void**)&qrh, g_qr_hi);  cudaGetSymbolAddress((void**)&qrl, g_qr_lo);
    cudaGetSymbolAddress((void**)&krh, g_kr_hi);  cudaGetSymbolAddress((void**)&krl, g_kr_lo);
    cudaGetSymbolAddress((void**)&vsh, g_vs_hi);  cudaGetSymbolAddress((void**)&vsl, g_vs_lo);

    // split conversions (weights concatenated into g_wqkv)
    {
        long n4;
        n4 = (long)Mv * Dv / 4;
        cvt_split<<<(unsigned)((n4 + 255) / 256), 256>>>(x, xh, xl, n4);
        n4 = (long)NQ * Dv / 4;
        cvt_split<<<(unsigned)((n4 + 255) / 256), 256>>>(wq, wh, wl, n4);
        n4 = (long)NKV * Dv / 4;
        cvt_split<<<(unsigned)((n4 + 255) / 256), 256>>>(
            wk, wh + (size_t)NQ * Dv, wl + (size_t)NQ * Dv, n4);
        cvt_split<<<(unsigned)((n4 + 255) / 256), 256>>>(
            wv, wh + (size_t)(NQ + NKV) * Dv, wl + (size_t)(NQ + NKV) * Dv, n4);
        n4 = (long)Dv * NQ / 4;
        cvt_split<<<(unsigned)((n4 + 255) / 256), 256>>>(wo, oh, ol, n4);
    }

    cudaFuncSetAttribute(gemm_hmma_x3<true>,
                         cudaFuncAttributeMaxDynamicSharedMemorySize, GEMM_SMEM);
    cudaFuncSetAttribute(gemm_hmma_x3<false>,
                         cudaFuncAttributeMaxDynamicSharedMemorySize, GEMM_SMEM);

    // Fused QKV projection + RoPE + split
    gemm_hmma_x3<true><<<dim3(NQKV / BN, Mv / BM), 256, GEMM_SMEM>>>(
        xh, xl, wh, wl, nullptr,
        qrh, qrl, krh, krl, vsh, vsl, fc, fs, NQKV, Dv);

    // HMMA flash attention v2 (2 CTAs/SM, 64 q-rows per CTA)
    cudaFuncSetAttribute(flash_hmma, cudaFuncAttributeMaxDynamicSharedMemorySize, FLASH_SMEM);
    flash_hmma<<<dim3(Sv / 64, Hv, Bv), 128, FLASH_SMEM>>>(
        qrh, qrl, krh, krl, vsh, vsl, ah, al);

    // Output projection
    gemm_hmma_x3<false><<<dim3(NQ / BN, Mv / BM), 256, GEMM_SMEM>>>(
        ah, al, oh, ol, out,
        nullptr, nullptr, nullptr, nullptr, nullptr, nullptr, nullptr, nullptr,
        NQ, Dv);
}